// round 2
// baseline (speedup 1.0000x reference)
#include <cuda_runtime.h>
#include <math.h>

#define R_DIM 64
#define I_DIM 512
#define N_DIM 4
#define E_DIM 256
#define H_DIM 8
#define D_DIM 32
#define T_TOK (R_DIM * I_DIM * N_DIM)                 /* 131072 tokens */
#define OUT_ELEMS ((size_t)T_TOK * E_DIM)             /* 33554432 */
#define PROB_ELEMS ((size_t)H_DIM * N_DIM * I_DIM * I_DIM) /* 8388608 */

// ---------------- scratch (alloc-free rule: __device__ globals) ----------------
__device__ float g_q[T_TOK * E_DIM];
__device__ float g_k[T_TOK * E_DIM];
__device__ float g_v[T_TOK * E_DIM];
__device__ float g_ctx[T_TOK * E_DIM];
__device__ float g_probs[PROB_ELEMS];   // fallback only if d_out lacks probs region

// ---------------- shared 8x8 microkernel over [8][132]-padded tiles ------------
__device__ __forceinline__ void mm8x8(const float (*As)[132], const float (*Bs)[132],
                                      int ty, int tx, float acc[8][8]) {
#pragma unroll
    for (int kk = 0; kk < 8; kk++) {
        float4 alo = *(const float4*)&As[kk][ty * 4];
        float4 ahi = *(const float4*)&As[kk][64 + ty * 4];
        float4 blo = *(const float4*)&Bs[kk][tx * 4];
        float4 bhi = *(const float4*)&Bs[kk][64 + tx * 4];
        float av[8] = {alo.x, alo.y, alo.z, alo.w, ahi.x, ahi.y, ahi.z, ahi.w};
        float bv[8] = {blo.x, blo.y, blo.z, blo.w, bhi.x, bhi.y, bhi.z, bhi.w};
#pragma unroll
        for (int u = 0; u < 8; u++)
#pragma unroll
            for (int v = 0; v < 8; v++)
                acc[u][v] = fmaf(av[u], bv[v], acc[u][v]);
    }
}

// T5 bucketize: first idx in [0,62] with linspace(0,50000,63)[idx] >= |d|, else 63.
// |d| < 50000 always (randint upper bound exclusive) -> result <= 62.
__device__ __forceinline__ int bucket_of(int dist) {
    int ad = dist < 0 ? -dist : dist;
    float v = (float)ad;
    int lo = 0, hi = 62;
#pragma unroll
    for (int it = 0; it < 6; it++) {
        int mid = (lo + hi) >> 1;
        float b = (float)((50000.0 * (double)mid) / 62.0);
        if (b >= v) hi = mid; else lo = mid + 1;
    }
    return lo;
}

// ---------------- projection: C[t,f] = (sum_e A[t,e] W[f,e] + b[f]) * scale -----
__global__ __launch_bounds__(256) void proj_kernel(
    const float* __restrict__ A, const float* __restrict__ W,
    const float* __restrict__ bias, float* __restrict__ C, float scale)
{
    __shared__ float As[8][132];
    __shared__ float Ws[8][132];
    const int tid = threadIdx.x;
    const int t0 = blockIdx.x * 128;
    const int f0 = blockIdx.y * 128;
    const int row = tid >> 1;
    const int c4 = (tid & 1) * 4;
    const int tx = tid & 15;
    const int ty = tid >> 4;

    float acc[8][8];
#pragma unroll
    for (int u = 0; u < 8; u++)
#pragma unroll
        for (int v = 0; v < 8; v++) acc[u][v] = 0.f;

    const float* Ap = A + (size_t)(t0 + row) * E_DIM + c4;
    const float* Wp = W + (size_t)(f0 + row) * E_DIM + c4;

    for (int e0 = 0; e0 < E_DIM; e0 += 8) {
        float4 a = *(const float4*)(Ap + e0);
        float4 w = *(const float4*)(Wp + e0);
        As[c4 + 0][row] = a.x; As[c4 + 1][row] = a.y; As[c4 + 2][row] = a.z; As[c4 + 3][row] = a.w;
        Ws[c4 + 0][row] = w.x; Ws[c4 + 1][row] = w.y; Ws[c4 + 2][row] = w.z; Ws[c4 + 3][row] = w.w;
        __syncthreads();
        mm8x8(As, Ws, ty, tx, acc);
        __syncthreads();
    }

#pragma unroll
    for (int uh = 0; uh < 2; uh++)
#pragma unroll
        for (int u = 0; u < 4; u++) {
            int r = t0 + uh * 64 + ty * 4 + u;
            float* Crow = C + (size_t)r * E_DIM;
#pragma unroll
            for (int vh = 0; vh < 2; vh++) {
                int cb = f0 + vh * 64 + tx * 4;
                float4 o;
                o.x = (acc[uh * 4 + u][vh * 4 + 0] + bias[cb + 0]) * scale;
                o.y = (acc[uh * 4 + u][vh * 4 + 1] + bias[cb + 1]) * scale;
                o.z = (acc[uh * 4 + u][vh * 4 + 2] + bias[cb + 2]) * scale;
                o.w = (acc[uh * 4 + u][vh * 4 + 3] + bias[cb + 3]) * scale;
                *(float4*)(Crow + cb) = o;
            }
        }
}

// ------------- logits: out[h,n,i,j] = sum_{r,d} q[r,i,n,h,d] k[r,j,n,h,d] + bias -
__global__ __launch_bounds__(256) void logits_kernel(
    const float* __restrict__ q, const float* __restrict__ k,
    const int* __restrict__ dist, const float* __restrict__ rel,
    float* __restrict__ out)
{
    __shared__ float Qs[8][132];
    __shared__ float Ks[8][132];
    const int tid = threadIdx.x;
    const int z = blockIdx.z;       // 0..31
    const int h = z >> 2;
    const int n = z & 3;
    const int i0 = blockIdx.x * 128;
    const int j0 = blockIdx.y * 128;
    const int row = tid >> 1;
    const int c4 = (tid & 1) * 4;
    const int tx = tid & 15;
    const int ty = tid >> 4;

    float acc[8][8];
#pragma unroll
    for (int u = 0; u < 8; u++)
#pragma unroll
        for (int v = 0; v < 8; v++) acc[u][v] = 0.f;

    // token layout: (((r*512 + i)*4 + n)*256 + h*32 + d)
    const float* qb = q + ((size_t)(i0 + row) * 1024) + (size_t)n * 256 + h * 32 + c4;
    const float* kb = k + ((size_t)(j0 + row) * 1024) + (size_t)n * 256 + h * 32 + c4;

    for (int kt = 0; kt < 256; kt++) {
        int r = kt >> 2;
        int d0 = (kt & 3) * 8;
        size_t off = (size_t)r * 524288 + d0;   // r * (512*1024)
        float4 a = *(const float4*)(qb + off);
        float4 b = *(const float4*)(kb + off);
        Qs[c4 + 0][row] = a.x; Qs[c4 + 1][row] = a.y; Qs[c4 + 2][row] = a.z; Qs[c4 + 3][row] = a.w;
        Ks[c4 + 0][row] = b.x; Ks[c4 + 1][row] = b.y; Ks[c4 + 2][row] = b.z; Ks[c4 + 3][row] = b.w;
        __syncthreads();
        mm8x8(Qs, Ks, ty, tx, acc);
        __syncthreads();
    }

#pragma unroll
    for (int uh = 0; uh < 2; uh++)
#pragma unroll
        for (int u = 0; u < 4; u++) {
            int i = i0 + uh * 64 + ty * 4 + u;
            const int* drow = dist + (size_t)n * I_DIM * I_DIM + (size_t)i * I_DIM;
            float* orow = out + ((size_t)(h * 4 + n) * I_DIM + i) * I_DIM;
#pragma unroll
            for (int vh = 0; vh < 2; vh++) {
                int jb = j0 + vh * 64 + tx * 4;
                float4 o;
                o.x = acc[uh * 4 + u][vh * 4 + 0] + rel[bucket_of(drow[jb + 0]) * H_DIM + h];
                o.y = acc[uh * 4 + u][vh * 4 + 1] + rel[bucket_of(drow[jb + 1]) * H_DIM + h];
                o.z = acc[uh * 4 + u][vh * 4 + 2] + rel[bucket_of(drow[jb + 2]) * H_DIM + h];
                o.w = acc[uh * 4 + u][vh * 4 + 3] + rel[bucket_of(drow[jb + 3]) * H_DIM + h];
                *(float4*)(orow + jb) = o;
            }
        }
}

// ---------------- softmax over last dim (512), in place -------------------------
__global__ __launch_bounds__(128) void softmax_kernel(float* __restrict__ P) {
    float* p = P + (size_t)blockIdx.x * 512;
    const int tid = threadIdx.x;
    const int w = tid >> 5, lane = tid & 31;
    __shared__ float red[4];

    float4 xv = ((float4*)p)[tid];
    float m = fmaxf(fmaxf(xv.x, xv.y), fmaxf(xv.z, xv.w));
#pragma unroll
    for (int o = 16; o > 0; o >>= 1) m = fmaxf(m, __shfl_xor_sync(0xffffffffu, m, o));
    if (lane == 0) red[w] = m;
    __syncthreads();
    m = fmaxf(fmaxf(red[0], red[1]), fmaxf(red[2], red[3]));
    __syncthreads();

    float4 ev;
    ev.x = expf(xv.x - m); ev.y = expf(xv.y - m);
    ev.z = expf(xv.z - m); ev.w = expf(xv.w - m);
    float s = ev.x + ev.y + ev.z + ev.w;
#pragma unroll
    for (int o = 16; o > 0; o >>= 1) s += __shfl_xor_sync(0xffffffffu, s, o);
    if (lane == 0) red[w] = s;
    __syncthreads();
    s = red[0] + red[1] + red[2] + red[3];
    float inv = 1.0f / s;
    ev.x *= inv; ev.y *= inv; ev.z *= inv; ev.w *= inv;
    ((float4*)p)[tid] = ev;
}

// --------- context: ctx[r,i,n,h,d] = sum_j P[h,n,i,j] v[r,j,n,h,d] --------------
// Per (n,h): OUT[i, c] with c=(r_local,d) packed 128-wide; K-dim = j (512).
__global__ __launch_bounds__(256) void context_kernel(
    const float* __restrict__ P, const float* __restrict__ V, float* __restrict__ ctx)
{
    __shared__ float Ps[8][132];
    __shared__ float Vs[8][132];
    const int tid = threadIdx.x;
    const int z = blockIdx.z;
    const int h = z >> 2;
    const int n = z & 3;
    const int i0 = blockIdx.x * 128;
    const int c0 = blockIdx.y * 128;     // over r*32+d (2048 wide)
    const int r0 = c0 >> 5;              // 4 r values per tile
    const int row = tid >> 1;
    const int c4 = (tid & 1) * 4;
    const int tx = tid & 15;
    const int ty = tid >> 4;

    // V loader mapping: 256 float4 loads cover Bs[8 j][128 c]
    const int d4 = (tid & 7) * 4;
    const int rl = (tid >> 3) & 3;
    const int jl = tid >> 5;

    float acc[8][8];
#pragma unroll
    for (int u = 0; u < 8; u++)
#pragma unroll
        for (int v = 0; v < 8; v++) acc[u][v] = 0.f;

    const float* Pb = P + ((size_t)(h * 4 + n) * I_DIM + i0 + row) * I_DIM + c4;
    const float* Vb = V + (((size_t)(r0 + rl) * I_DIM + jl) * 4 + n) * 256 + h * 32 + d4;

    for (int kt = 0; kt < 64; kt++) {
        int jb = kt * 8;
        float4 a = *(const float4*)(Pb + jb);
        float4 b = *(const float4*)(Vb + (size_t)jb * 1024);
        Ps[c4 + 0][row] = a.x; Ps[c4 + 1][row] = a.y; Ps[c4 + 2][row] = a.z; Ps[c4 + 3][row] = a.w;
        int cc = rl * 32 + d4;
        Vs[jl][cc + 0] = b.x; Vs[jl][cc + 1] = b.y; Vs[jl][cc + 2] = b.z; Vs[jl][cc + 3] = b.w;
        __syncthreads();
        mm8x8(Ps, Vs, ty, tx, acc);
        __syncthreads();
    }

#pragma unroll
    for (int uh = 0; uh < 2; uh++)
#pragma unroll
        for (int u = 0; u < 4; u++) {
            int i = i0 + uh * 64 + ty * 4 + u;
#pragma unroll
            for (int vh = 0; vh < 2; vh++) {
                int c = c0 + vh * 64 + tx * 4;
                int r = c >> 5, d = c & 31;
                float4 o;
                o.x = acc[uh * 4 + u][vh * 4 + 0];
                o.y = acc[uh * 4 + u][vh * 4 + 1];
                o.z = acc[uh * 4 + u][vh * 4 + 2];
                o.w = acc[uh * 4 + u][vh * 4 + 3];
                *(float4*)(ctx + (((size_t)r * I_DIM + i) * 4 + n) * 256 + h * 32 + d) = o;
            }
        }
}

// --------------------------------- launch ---------------------------------------
extern "C" void kernel_launch(void* const* d_in, const int* in_sizes, int n_in,
                              void* d_out, int out_size) {
    const float* x   = (const float*)d_in[0];
    const int*   dst = (const int*)  d_in[1];
    const float* Wq  = (const float*)d_in[2];
    const float* bq  = (const float*)d_in[3];
    const float* Wk  = (const float*)d_in[4];
    const float* bk  = (const float*)d_in[5];
    const float* Wv  = (const float*)d_in[6];
    const float* bv  = (const float*)d_in[7];
    const float* Wo  = (const float*)d_in[8];
    const float* bo  = (const float*)d_in[9];
    const float* rel = (const float*)d_in[10];
    float* out = (float*)d_out;

    float *q, *k, *v, *ctx, *probs_fallback;
    cudaGetSymbolAddress((void**)&q,   g_q);
    cudaGetSymbolAddress((void**)&k,   g_k);
    cudaGetSymbolAddress((void**)&v,   g_v);
    cudaGetSymbolAddress((void**)&ctx, g_ctx);
    cudaGetSymbolAddress((void**)&probs_fallback, g_probs);

    float* probs = ((size_t)out_size >= OUT_ELEMS + PROB_ELEMS) ? (out + OUT_ELEMS)
                                                                : probs_fallback;

    // scaling = D^-0.5 / sqrt(R) applied to q after bias (matches reference order)
    const float scaleq = 0.022097086912079608f;

    dim3 blk(256);
    proj_kernel<<<dim3(T_TOK / 128, E_DIM / 128), blk>>>(x, Wq, bq, q, scaleq);
    proj_kernel<<<dim3(T_TOK / 128, E_DIM / 128), blk>>>(x, Wk, bk, k, 1.0f);
    proj_kernel<<<dim3(T_TOK / 128, E_DIM / 128), blk>>>(x, Wv, bv, v, 1.0f);

    logits_kernel<<<dim3(I_DIM / 128, I_DIM / 128, N_DIM * H_DIM), blk>>>(q, k, dst, rel, probs);
    softmax_kernel<<<H_DIM * N_DIM * I_DIM, 128>>>(probs);
    context_kernel<<<dim3(I_DIM / 128, (R_DIM * D_DIM) / 128, N_DIM * H_DIM), blk>>>(probs, v, ctx);

    proj_kernel<<<dim3(T_TOK / 128, E_DIM / 128), blk>>>(ctx, Wo, bo, out, 1.0f);
}

// round 3
// speedup vs baseline: 1.9655x; 1.9655x over previous
#include <cuda_runtime.h>
#include <math.h>

#define R_DIM 64
#define I_DIM 512
#define N_DIM 4
#define E_DIM 256
#define H_DIM 8
#define D_DIM 32
#define T_TOK (R_DIM * I_DIM * N_DIM)                 /* 131072 tokens */
#define OUT_ELEMS ((size_t)T_TOK * E_DIM)             /* 33554432 */
#define PROB_ELEMS ((size_t)H_DIM * N_DIM * I_DIM * I_DIM) /* 8388608 */
#define PAD 136

// ---------------- scratch (alloc-free rule: __device__ globals) ----------------
__device__ float g_q[T_TOK * E_DIM];
__device__ float g_k[T_TOK * E_DIM];
__device__ float g_v[T_TOK * E_DIM];
__device__ float g_ctx[T_TOK * E_DIM];
__device__ float g_probs[PROB_ELEMS];
__device__ unsigned char g_bkt[N_DIM * I_DIM * I_DIM];

// ---------------- tf32 helpers --------------------------------------------------
__device__ __forceinline__ float f2tff(float x) {
    unsigned u;
    asm("cvt.rna.tf32.f32 %0, %1;" : "=r"(u) : "f"(x));
    return __uint_as_float(u);
}

__device__ __forceinline__ void mma_tf32(float c[4],
    unsigned a0, unsigned a1, unsigned a2, unsigned a3, unsigned b0, unsigned b1) {
    asm volatile(
        "mma.sync.aligned.m16n8k8.row.col.f32.tf32.tf32.f32 "
        "{%0,%1,%2,%3}, {%4,%5,%6,%7}, {%8,%9}, {%0,%1,%2,%3};"
        : "+f"(c[0]), "+f"(c[1]), "+f"(c[2]), "+f"(c[3])
        : "r"(a0), "r"(a1), "r"(a2), "r"(a3), "r"(b0), "r"(b1));
}

// One KK=16 chunk: each warp computes its 64x32 tile (4x4 m16n8k8 frags, 2 k-steps)
__device__ __forceinline__ void compute_chunk(
    const float (*As)[PAD], const float (*Bs)[PAD],
    int wm, int wn, int grp, int qid, float acc[4][4][4]) {
#pragma unroll
    for (int ks = 0; ks < 16; ks += 8) {
        unsigned a[4][4], b[4][2];
#pragma unroll
        for (int f = 0; f < 4; f++) {
            int row = wm + f * 16 + grp;
            a[f][0] = __float_as_uint(As[ks + qid][row]);
            a[f][1] = __float_as_uint(As[ks + qid][row + 8]);
            a[f][2] = __float_as_uint(As[ks + qid + 4][row]);
            a[f][3] = __float_as_uint(As[ks + qid + 4][row + 8]);
        }
#pragma unroll
        for (int g = 0; g < 4; g++) {
            int col = wn + g * 8 + grp;
            b[g][0] = __float_as_uint(Bs[ks + qid][col]);
            b[g][1] = __float_as_uint(Bs[ks + qid + 4][col]);
        }
#pragma unroll
        for (int f = 0; f < 4; f++)
#pragma unroll
            for (int g = 0; g < 4; g++)
                mma_tf32(acc[f][g], a[f][0], a[f][1], a[f][2], a[f][3], b[g][0], b[g][1]);
    }
}

__device__ __forceinline__ void sts8(float (*S)[PAD], int k0, int row,
                                     const float4& v0, const float4& v1) {
    S[k0 + 0][row] = f2tff(v0.x); S[k0 + 1][row] = f2tff(v0.y);
    S[k0 + 2][row] = f2tff(v0.z); S[k0 + 3][row] = f2tff(v0.w);
    S[k0 + 4][row] = f2tff(v1.x); S[k0 + 5][row] = f2tff(v1.y);
    S[k0 + 6][row] = f2tff(v1.z); S[k0 + 7][row] = f2tff(v1.w);
}

// T5 bucketize (exact match to jnp.linspace/searchsorted — verified in R2)
__device__ __forceinline__ int bucket_of(int dist) {
    int ad = dist < 0 ? -dist : dist;
    float v = (float)ad;
    int lo = 0, hi = 62;
#pragma unroll
    for (int it = 0; it < 6; it++) {
        int mid = (lo + hi) >> 1;
        float b = (float)((50000.0 * (double)mid) / 62.0);
        if (b >= v) hi = mid; else lo = mid + 1;
    }
    return lo;
}

__global__ __launch_bounds__(256) void bucket_kernel(
    const int* __restrict__ dist, unsigned char* __restrict__ bkt) {
    int idx = blockIdx.x * 256 + threadIdx.x;
    bkt[idx] = (unsigned char)bucket_of(dist[idx]);
}

// ---------------- projection: C[t,f] = (sum_e A[t,e] W[f,e] + b[f]) * scale -----
__global__ __launch_bounds__(256) void proj_tc(
    const float* __restrict__ A, const float* __restrict__ W,
    const float* __restrict__ bias, float* __restrict__ C, float scale)
{
    __shared__ float As[16][PAD];
    __shared__ float Bs[16][PAD];
    const int tid = threadIdx.x;
    const int warp = tid >> 5, lane = tid & 31, grp = lane >> 2, qid = lane & 3;
    const int wm = (warp >> 2) * 64, wn = (warp & 3) * 32;
    const int t0 = blockIdx.x * 128, f0 = blockIdx.y * 128;
    const int row = tid >> 1, k0 = (tid & 1) * 8;

    float acc[4][4][4];
#pragma unroll
    for (int f = 0; f < 4; f++)
#pragma unroll
        for (int g = 0; g < 4; g++)
#pragma unroll
            for (int c = 0; c < 4; c++) acc[f][g][c] = 0.f;

    const float* Ap = A + (size_t)(t0 + row) * E_DIM + k0;
    const float* Wp = W + (size_t)(f0 + row) * E_DIM + k0;

    float4 pa0 = *(const float4*)Ap,       pa1 = *(const float4*)(Ap + 4);
    float4 pb0 = *(const float4*)Wp,       pb1 = *(const float4*)(Wp + 4);

    for (int ch = 0; ch < 16; ch++) {
        sts8(As, k0, row, pa0, pa1);
        sts8(Bs, k0, row, pb0, pb1);
        __syncthreads();
        if (ch < 15) {
            int e = (ch + 1) * 16;
            pa0 = *(const float4*)(Ap + e); pa1 = *(const float4*)(Ap + e + 4);
            pb0 = *(const float4*)(Wp + e); pb1 = *(const float4*)(Wp + e + 4);
        }
        compute_chunk(As, Bs, wm, wn, grp, qid, acc);
        __syncthreads();
    }

#pragma unroll
    for (int f = 0; f < 4; f++)
#pragma unroll
        for (int rr = 0; rr < 2; rr++) {
            int i = t0 + wm + f * 16 + grp + rr * 8;
            float* Crow = C + (size_t)i * E_DIM;
#pragma unroll
            for (int g = 0; g < 4; g++) {
                int col = wn + g * 8 + qid * 2;
                float2 o;
                o.x = (acc[f][g][rr * 2 + 0] + bias[f0 + col + 0]) * scale;
                o.y = (acc[f][g][rr * 2 + 1] + bias[f0 + col + 1]) * scale;
                *(float2*)(Crow + f0 + col) = o;
            }
        }
}

// ------------- logits: out[h,n,i,j] = sum_{r,d} q[.] k[.] + rel[bucket[n,i,j],h] -
__global__ __launch_bounds__(256) void logits_tc(
    const float* __restrict__ q, const float* __restrict__ k,
    const unsigned char* __restrict__ bkt, const float* __restrict__ rel,
    float* __restrict__ out)
{
    __shared__ float As[16][PAD];
    __shared__ float Bs[16][PAD];
    const int tid = threadIdx.x;
    const int warp = tid >> 5, lane = tid & 31, grp = lane >> 2, qid = lane & 3;
    const int wm = (warp >> 2) * 64, wn = (warp & 3) * 32;
    const int z = blockIdx.z;
    const int h = z >> 2, n = z & 3;
    const int i0 = blockIdx.x * 128, j0 = blockIdx.y * 128;
    const int row = tid >> 1, k0 = (tid & 1) * 8;

    float acc[4][4][4];
#pragma unroll
    for (int f = 0; f < 4; f++)
#pragma unroll
        for (int g = 0; g < 4; g++)
#pragma unroll
            for (int c = 0; c < 4; c++) acc[f][g][c] = 0.f;

    // token layout: (((r*512 + i)*4 + n)*256 + h*32 + d); r stride = 524288
    const float* qb = q + ((size_t)(i0 + row) * 4 + n) * 256 + h * 32 + k0;
    const float* kb = k + ((size_t)(j0 + row) * 4 + n) * 256 + h * 32 + k0;

    size_t off0 = 0;                                    // chunk 0: r=0, d0=0
    float4 pa0 = *(const float4*)(qb), pa1 = *(const float4*)(qb + 4);
    float4 pb0 = *(const float4*)(kb), pb1 = *(const float4*)(kb + 4);
    (void)off0;

    for (int ch = 0; ch < 128; ch++) {
        sts8(As, k0, row, pa0, pa1);
        sts8(Bs, k0, row, pb0, pb1);
        __syncthreads();
        if (ch < 127) {
            int cn = ch + 1;
            size_t off = (size_t)(cn >> 1) * 524288 + (cn & 1) * 16;
            pa0 = *(const float4*)(qb + off); pa1 = *(const float4*)(qb + off + 4);
            pb0 = *(const float4*)(kb + off); pb1 = *(const float4*)(kb + off + 4);
        }
        compute_chunk(As, Bs, wm, wn, grp, qid, acc);
        __syncthreads();
    }

#pragma unroll
    for (int f = 0; f < 4; f++)
#pragma unroll
        for (int rr = 0; rr < 2; rr++) {
            int i = i0 + wm + f * 16 + grp + rr * 8;
            const unsigned char* brow = bkt + ((size_t)n * I_DIM + i) * I_DIM;
            float* orow = out + ((size_t)(h * 4 + n) * I_DIM + i) * I_DIM;
#pragma unroll
            for (int g = 0; g < 4; g++) {
                int j = j0 + wn + g * 8 + qid * 2;
                float2 o;
                o.x = acc[f][g][rr * 2 + 0] + rel[brow[j + 0] * H_DIM + h];
                o.y = acc[f][g][rr * 2 + 1] + rel[brow[j + 1] * H_DIM + h];
                *(float2*)(orow + j) = o;
            }
        }
}

// ---------------- softmax over last dim (512), in place -------------------------
__global__ __launch_bounds__(128) void softmax_kernel(float* __restrict__ P) {
    float* p = P + (size_t)blockIdx.x * 512;
    const int tid = threadIdx.x;
    const int w = tid >> 5, lane = tid & 31;
    __shared__ float red[4];

    float4 xv = ((float4*)p)[tid];
    float m = fmaxf(fmaxf(xv.x, xv.y), fmaxf(xv.z, xv.w));
#pragma unroll
    for (int o = 16; o > 0; o >>= 1) m = fmaxf(m, __shfl_xor_sync(0xffffffffu, m, o));
    if (lane == 0) red[w] = m;
    __syncthreads();
    m = fmaxf(fmaxf(red[0], red[1]), fmaxf(red[2], red[3]));
    __syncthreads();

    float4 ev;
    ev.x = expf(xv.x - m); ev.y = expf(xv.y - m);
    ev.z = expf(xv.z - m); ev.w = expf(xv.w - m);
    float s = ev.x + ev.y + ev.z + ev.w;
#pragma unroll
    for (int o = 16; o > 0; o >>= 1) s += __shfl_xor_sync(0xffffffffu, s, o);
    if (lane == 0) red[w] = s;
    __syncthreads();
    s = red[0] + red[1] + red[2] + red[3];
    float inv = 1.0f / s;
    ev.x *= inv; ev.y *= inv; ev.z *= inv; ev.w *= inv;
    ((float4*)p)[tid] = ev;
}

// --------- context: ctx[r,i,n,h,d] = sum_j P[h,n,i,j] v[r,j,n,h,d] --------------
__global__ __launch_bounds__(256) void context_tc(
    const float* __restrict__ P, const float* __restrict__ V, float* __restrict__ ctx)
{
    __shared__ float As[16][PAD];
    __shared__ float Bs[16][PAD];
    const int tid = threadIdx.x;
    const int warp = tid >> 5, lane = tid & 31, grp = lane >> 2, qid = lane & 3;
    const int wm = (warp >> 2) * 64, wn = (warp & 3) * 32;
    const int z = blockIdx.z;
    const int h = z >> 2, n = z & 3;
    const int i0 = blockIdx.x * 128;
    const int c0 = blockIdx.y * 128;     // over r*32+d (2048 wide)
    const int r0 = c0 >> 5;              // 4 r values per tile

    // A loader (P, transpose into k-major)
    const int row = tid >> 1, k0 = (tid & 1) * 8;
    // B loader (V, already k(j)-minor per column group): 16 j x 128 c per chunk
    const int jj = tid >> 4;             // 0..15
    const int inner = tid & 15;
    const int col0 = inner * 8;
    const int rl = col0 >> 5, d0 = col0 & 31;

    float acc[4][4][4];
#pragma unroll
    for (int f = 0; f < 4; f++)
#pragma unroll
        for (int g = 0; g < 4; g++)
#pragma unroll
            for (int c = 0; c < 4; c++) acc[f][g][c] = 0.f;

    const float* Pb = P + ((size_t)(h * 4 + n) * I_DIM + i0 + row) * I_DIM + k0;
    const float* Vb = V + (((size_t)(r0 + rl) * I_DIM + jj) * 4 + n) * 256 + h * 32 + d0;

    float4 pa0 = *(const float4*)(Pb),  pa1 = *(const float4*)(Pb + 4);
    float4 pb0 = *(const float4*)(Vb),  pb1 = *(const float4*)(Vb + 4);

    for (int ch = 0; ch < 32; ch++) {
        sts8(As, k0, row, pa0, pa1);
        {   // contiguous tf32 store for V tile
            float4 c0v = make_float4(f2tff(pb0.x), f2tff(pb0.y), f2tff(pb0.z), f2tff(pb0.w));
            float4 c1v = make_float4(f2tff(pb1.x), f2tff(pb1.y), f2tff(pb1.z), f2tff(pb1.w));
            *(float4*)&Bs[jj][col0]     = c0v;
            *(float4*)&Bs[jj][col0 + 4] = c1v;
        }
        __syncthreads();
        if (ch < 31) {
            int cn = ch + 1;
            pa0 = *(const float4*)(Pb + cn * 16);
            pa1 = *(const float4*)(Pb + cn * 16 + 4);
            size_t voff = (size_t)cn * 16384;  // 16 j * 1024 floats/j
            pb0 = *(const float4*)(Vb + voff);
            pb1 = *(const float4*)(Vb + voff + 4);
        }
        compute_chunk(As, Bs, wm, wn, grp, qid, acc);
        __syncthreads();
    }

#pragma unroll
    for (int f = 0; f < 4; f++)
#pragma unroll
        for (int rr = 0; rr < 2; rr++) {
            int i = i0 + wm + f * 16 + grp + rr * 8;
#pragma unroll
            for (int g = 0; g < 4; g++) {
                int col = c0 + wn + g * 8 + qid * 2;
                int r = col >> 5, d = col & 31;
                float2 o;
                o.x = acc[f][g][rr * 2 + 0];
                o.y = acc[f][g][rr * 2 + 1];
                *(float2*)(ctx + (((size_t)r * I_DIM + i) * 4 + n) * 256 + h * 32 + d) = o;
            }
        }
}

// --------------------------------- launch ---------------------------------------
extern "C" void kernel_launch(void* const* d_in, const int* in_sizes, int n_in,
                              void* d_out, int out_size) {
    const float* x   = (const float*)d_in[0];
    const int*   dst = (const int*)  d_in[1];
    const float* Wq  = (const float*)d_in[2];
    const float* bq  = (const float*)d_in[3];
    const float* Wk  = (const float*)d_in[4];
    const float* bk  = (const float*)d_in[5];
    const float* Wv  = (const float*)d_in[6];
    const float* bv  = (const float*)d_in[7];
    const float* Wo  = (const float*)d_in[8];
    const float* bo  = (const float*)d_in[9];
    const float* rel = (const float*)d_in[10];
    float* out = (float*)d_out;

    float *q, *k, *v, *ctx, *probs_fallback;
    unsigned char* bkt;
    cudaGetSymbolAddress((void**)&q,   g_q);
    cudaGetSymbolAddress((void**)&k,   g_k);
    cudaGetSymbolAddress((void**)&v,   g_v);
    cudaGetSymbolAddress((void**)&ctx, g_ctx);
    cudaGetSymbolAddress((void**)&probs_fallback, g_probs);
    cudaGetSymbolAddress((void**)&bkt, g_bkt);

    float* probs = ((size_t)out_size >= OUT_ELEMS + PROB_ELEMS) ? (out + OUT_ELEMS)
                                                                : probs_fallback;

    const float scaleq = 0.022097086912079608f;  // D^-0.5 / sqrt(R)

    dim3 blk(256);
    bucket_kernel<<<(N_DIM * I_DIM * I_DIM) / 256, blk>>>(dst, bkt);

    proj_tc<<<dim3(T_TOK / 128, E_DIM / 128), blk>>>(x, Wq, bq, q, scaleq);
    proj_tc<<<dim3(T_TOK / 128, E_DIM / 128), blk>>>(x, Wk, bk, k, 1.0f);
    proj_tc<<<dim3(T_TOK / 128, E_DIM / 128), blk>>>(x, Wv, bv, v, 1.0f);

    logits_tc<<<dim3(I_DIM / 128, I_DIM / 128, N_DIM * H_DIM), blk>>>(q, k, bkt, rel, probs);
    softmax_kernel<<<H_DIM * N_DIM * I_DIM, 128>>>(probs);
    context_tc<<<dim3(I_DIM / 128, (R_DIM * D_DIM) / 128, N_DIM * H_DIM), blk>>>(probs, v, ctx);

    proj_tc<<<dim3(T_TOK / 128, E_DIM / 128), blk>>>(ctx, Wo, bo, out, 1.0f);
}

// round 5
// speedup vs baseline: 3.5807x; 1.8218x over previous
#include <cuda_runtime.h>
#include <cuda_fp16.h>
#include <math.h>
#include <stdint.h>

#define R_DIM 64
#define I_DIM 512
#define N_DIM 4
#define E_DIM 256
#define H_DIM 8
#define D_DIM 32
#define T_TOK (R_DIM * I_DIM * N_DIM)                 /* 131072 tokens */
#define OUT_ELEMS ((size_t)T_TOK * E_DIM)             /* 33554432 */
#define PROB_ELEMS ((size_t)H_DIM * N_DIM * I_DIM * I_DIM) /* 8388608 */

#define ROWB 80                    /* padded bytes per 32-half smem row */
#define TILE_BYTES (128 * ROWB)    /* 10240 */

// ---------------- scratch (alloc-free rule: __device__ globals) ----------------
__device__ __half gh_q[T_TOK * E_DIM];
__device__ __half gh_k[T_TOK * E_DIM];
__device__ __half gh_v[T_TOK * E_DIM];
__device__ __half gh_vt[T_TOK * E_DIM];   // V transposed: [nh][r*32+d][i], fp16
__device__ __half gh_ctx[T_TOK * E_DIM];
__device__ float g_probs[PROB_ELEMS];
__device__ unsigned char g_bkt[N_DIM * I_DIM * I_DIM];

// ---------------- low-level helpers ---------------------------------------------
__device__ __forceinline__ uint32_t smem_u32(const void* p) {
    uint32_t a;
    asm("{ .reg .u64 t; cvta.to.shared.u64 t, %1; cvt.u32.u64 %0, t; }" : "=r"(a) : "l"(p));
    return a;
}
__device__ __forceinline__ void ldsm4(uint32_t& r0, uint32_t& r1, uint32_t& r2, uint32_t& r3,
                                      uint32_t addr) {
    asm volatile("ldmatrix.sync.aligned.m8n8.x4.shared.b16 {%0,%1,%2,%3}, [%4];"
                 : "=r"(r0), "=r"(r1), "=r"(r2), "=r"(r3) : "r"(addr));
}
__device__ __forceinline__ void mma16816(float c[4], const uint32_t a[4], const uint32_t b[2]) {
    asm volatile(
        "mma.sync.aligned.m16n8k16.row.col.f32.f16.f16.f32 "
        "{%0,%1,%2,%3}, {%4,%5,%6,%7}, {%8,%9}, {%0,%1,%2,%3};"
        : "+f"(c[0]), "+f"(c[1]), "+f"(c[2]), "+f"(c[3])
        : "r"(a[0]), "r"(a[1]), "r"(a[2]), "r"(a[3]), "r"(b[0]), "r"(b[1]));
}

// ---------------- global->reg->smem tile movement (128 rows x 32 halves) --------
// f32 source: convert to half; f16 source: straight 16B copy.
template<bool F16>
__device__ __forceinline__ void g2r(const void* base, size_t stride, int tid,
                                    float4 f[2][2], uint4 h[2]) {
#pragma unroll
    for (int it = 0; it < 2; it++) {
        int idx = tid + it * 256;
        int row = idx >> 2, g = idx & 3;
        if (F16) {
            h[it] = *(const uint4*)((const __half*)base + (size_t)row * stride + g * 8);
        } else {
            const float* p = (const float*)base + (size_t)row * stride + g * 8;
            f[it][0] = *(const float4*)p;
            f[it][1] = *(const float4*)(p + 4);
        }
    }
}
template<bool F16>
__device__ __forceinline__ void r2s(char* sm, int tid, const float4 f[2][2], const uint4 h[2]) {
#pragma unroll
    for (int it = 0; it < 2; it++) {
        int idx = tid + it * 256;
        int row = idx >> 2, g = idx & 3;
        uint4 u;
        if (F16) {
            u = h[it];
        } else {
            __half2 a = __float22half2_rn(make_float2(f[it][0].x, f[it][0].y));
            __half2 b = __float22half2_rn(make_float2(f[it][0].z, f[it][0].w));
            __half2 c = __float22half2_rn(make_float2(f[it][1].x, f[it][1].y));
            __half2 d = __float22half2_rn(make_float2(f[it][1].z, f[it][1].w));
            u.x = *(uint32_t*)&a; u.y = *(uint32_t*)&b;
            u.z = *(uint32_t*)&c; u.w = *(uint32_t*)&d;
        }
        *(uint4*)(sm + row * ROWB + g * 16) = u;
    }
}

// --------- per-warp compute on one 32-deep K chunk: 12 LDSM.x4, 32 HMMA ---------
__device__ __forceinline__ void compute_chunk(uint32_t bufA, uint32_t bufB,
                                              int wm, int wn, int lane, float acc[4][4][4]) {
    uint32_t aoff = bufA + (uint32_t)((wm + (lane & 15)) * ROWB + ((lane >> 4) << 4));
    uint32_t boff = bufB + (uint32_t)((wn + ((lane >> 4) << 3) + (lane & 7)) * ROWB
                                      + (((lane >> 3) & 1) << 4));
#pragma unroll
    for (int ks = 0; ks < 2; ks++) {
        uint32_t a[4][4];
#pragma unroll
        for (int fq = 0; fq < 4; fq++)
            ldsm4(a[fq][0], a[fq][1], a[fq][2], a[fq][3], aoff + fq * (16 * ROWB) + ks * 32);
        uint32_t b[4][2];
#pragma unroll
        for (int p = 0; p < 2; p++) {
            uint32_t r0, r1, r2, r3;
            ldsm4(r0, r1, r2, r3, boff + p * (16 * ROWB) + ks * 32);
            b[p * 2][0] = r0; b[p * 2][1] = r1;
            b[p * 2 + 1][0] = r2; b[p * 2 + 1][1] = r3;
        }
#pragma unroll
        for (int fq = 0; fq < 4; fq++)
#pragma unroll
            for (int g = 0; g < 4; g++)
                mma16816(acc[fq][g], a[fq], b[g]);
    }
}

// T5 bucketize (verified exact vs jnp.linspace/searchsorted in R2/R3)
__device__ __forceinline__ int bucket_of(int dist) {
    int ad = dist < 0 ? -dist : dist;
    float v = (float)ad;
    int lo = 0, hi = 62;
#pragma unroll
    for (int it = 0; it < 6; it++) {
        int mid = (lo + hi) >> 1;
        float b = (float)((50000.0 * (double)mid) / 62.0);
        if (b >= v) hi = mid; else lo = mid + 1;
    }
    return lo;
}
__global__ __launch_bounds__(256) void bucket_kernel(
    const int* __restrict__ dist, unsigned char* __restrict__ bkt) {
    int idx = blockIdx.x * 256 + threadIdx.x;
    bkt[idx] = (unsigned char)bucket_of(dist[idx]);
}

// ==================== projection: C[t,f] = (A·W^T + b)*scale ====================
template<bool A16, bool O16>
__global__ __launch_bounds__(256) void proj_gemm(
    const void* __restrict__ A, const float* __restrict__ W,
    const float* __restrict__ bias, void* __restrict__ C, float scale)
{
    __shared__ __align__(16) char smA[2][TILE_BYTES];
    __shared__ __align__(16) char smB[2][TILE_BYTES];
    const int tid = threadIdx.x, warp = tid >> 5, lane = tid & 31;
    const int wm = (warp >> 2) * 64, wn = (warp & 3) * 32;
    const int t0 = blockIdx.x * 128, f0 = blockIdx.y * 128;

    float acc[4][4][4];
#pragma unroll
    for (int fq = 0; fq < 4; fq++)
#pragma unroll
        for (int g = 0; g < 4; g++)
#pragma unroll
            for (int c = 0; c < 4; c++) acc[fq][g][c] = 0.f;

    const size_t Aoff0 = (size_t)t0 * E_DIM;
    const size_t Boff0 = (size_t)f0 * E_DIM;
    float4 pf[2][2]; uint4 ph[2];
    float4 bf[2][2]; uint4 bh[2];

    const void* Abase = A16 ? (const void*)((const __half*)A + Aoff0)
                            : (const void*)((const float*)A + Aoff0);
    g2r<A16>(Abase, E_DIM, tid, pf, ph);
    g2r<false>(W + Boff0, E_DIM, tid, bf, bh);
    r2s<A16>(smA[0], tid, pf, ph);
    r2s<false>(smB[0], tid, bf, bh);
    __syncthreads();

    uint32_t sA[2] = {smem_u32(smA[0]), smem_u32(smA[1])};
    uint32_t sB[2] = {smem_u32(smB[0]), smem_u32(smB[1])};

    const int NCH = E_DIM / 32;   // 8
    for (int ch = 0; ch < NCH; ch++) {
        if (ch + 1 < NCH) {
            const void* Ab = A16 ? (const void*)((const __half*)A + Aoff0 + (ch + 1) * 32)
                                 : (const void*)((const float*)A + Aoff0 + (ch + 1) * 32);
            g2r<A16>(Ab, E_DIM, tid, pf, ph);
            g2r<false>(W + Boff0 + (ch + 1) * 32, E_DIM, tid, bf, bh);
        }
        compute_chunk(sA[ch & 1], sB[ch & 1], wm, wn, lane, acc);
        if (ch + 1 < NCH) {
            r2s<A16>(smA[(ch + 1) & 1], tid, pf, ph);
            r2s<false>(smB[(ch + 1) & 1], tid, bf, bh);
        }
        __syncthreads();
    }

    const int grp = lane >> 2, qid = lane & 3;
#pragma unroll
    for (int fq = 0; fq < 4; fq++)
#pragma unroll
        for (int rr = 0; rr < 2; rr++) {
            int i = t0 + wm + fq * 16 + grp + rr * 8;
#pragma unroll
            for (int g = 0; g < 4; g++) {
                int col = f0 + wn + g * 8 + qid * 2;
                float2 o;
                o.x = (acc[fq][g][rr * 2 + 0] + bias[col + 0]) * scale;
                o.y = (acc[fq][g][rr * 2 + 1] + bias[col + 1]) * scale;
                if (O16) {
                    *(__half2*)((__half*)C + (size_t)i * E_DIM + col) = __float22half2_rn(o);
                } else {
                    *(float2*)((float*)C + (size_t)i * E_DIM + col) = o;
                }
            }
        }
}

// =========== logits: out[h,n,i,j] = sum_{r,d} q·k + rel[bucket[n,i,j],h] =========
__global__ __launch_bounds__(256) void logits_gemm(
    const __half* __restrict__ q, const __half* __restrict__ k,
    const unsigned char* __restrict__ bkt, const float* __restrict__ rel,
    float* __restrict__ out)
{
    __shared__ __align__(16) char smA[2][TILE_BYTES];
    __shared__ __align__(16) char smB[2][TILE_BYTES];
    const int tid = threadIdx.x, warp = tid >> 5, lane = tid & 31;
    const int wm = (warp >> 2) * 64, wn = (warp & 3) * 32;
    const int i0 = blockIdx.x * 128, j0 = blockIdx.y * 128;
    const int z = blockIdx.z, h = z >> 2, n = z & 3;

    float acc[4][4][4];
#pragma unroll
    for (int fq = 0; fq < 4; fq++)
#pragma unroll
        for (int g = 0; g < 4; g++)
#pragma unroll
            for (int c = 0; c < 4; c++) acc[fq][g][c] = 0.f;

    // token layout [t][f]: t=(r*512+i)*4+n, f=h*32+d; chunk ch = r (32 halves)
    const __half* Ab = q + ((size_t)i0 * 4 + n) * 256 + h * 32;
    const __half* Bb = k + ((size_t)j0 * 4 + n) * 256 + h * 32;
    float4 dummyf[2][2];
    uint4 pa[2], pb[2];

    g2r<true>(Ab, 1024, tid, dummyf, pa);
    g2r<true>(Bb, 1024, tid, dummyf, pb);
    r2s<true>(smA[0], tid, dummyf, pa);
    r2s<true>(smB[0], tid, dummyf, pb);
    __syncthreads();

    uint32_t sA[2] = {smem_u32(smA[0]), smem_u32(smA[1])};
    uint32_t sB[2] = {smem_u32(smB[0]), smem_u32(smB[1])};

    const int NCH = 64;   // r = 0..63
    for (int ch = 0; ch < NCH; ch++) {
        if (ch + 1 < NCH) {
            size_t off = (size_t)(ch + 1) * 524288;
            g2r<true>(Ab + off, 1024, tid, dummyf, pa);
            g2r<true>(Bb + off, 1024, tid, dummyf, pb);
        }
        compute_chunk(sA[ch & 1], sB[ch & 1], wm, wn, lane, acc);
        if (ch + 1 < NCH) {
            r2s<true>(smA[(ch + 1) & 1], tid, dummyf, pa);
            r2s<true>(smB[(ch + 1) & 1], tid, dummyf, pb);
        }
        __syncthreads();
    }

    const int grp = lane >> 2, qid = lane & 3;
#pragma unroll
    for (int fq = 0; fq < 4; fq++)
#pragma unroll
        for (int rr = 0; rr < 2; rr++) {
            int i = i0 + wm + fq * 16 + grp + rr * 8;
            const unsigned char* brow = bkt + ((size_t)n * I_DIM + i) * I_DIM;
            float* orow = out + ((size_t)(h * 4 + n) * I_DIM + i) * I_DIM;
#pragma unroll
            for (int g = 0; g < 4; g++) {
                int j = j0 + wn + g * 8 + qid * 2;
                float2 o;
                o.x = acc[fq][g][rr * 2 + 0] + rel[brow[j + 0] * H_DIM + h];
                o.y = acc[fq][g][rr * 2 + 1] + rel[brow[j + 1] * H_DIM + h];
                *(float2*)(orow + j) = o;
            }
        }
}

// ---------------- softmax over last dim (512), in place -------------------------
__global__ __launch_bounds__(128) void softmax_kernel(float* __restrict__ P) {
    float* p = P + (size_t)blockIdx.x * 512;
    const int tid = threadIdx.x;
    const int w = tid >> 5, lane = tid & 31;
    __shared__ float red[4];

    float4 xv = ((float4*)p)[tid];
    float m = fmaxf(fmaxf(xv.x, xv.y), fmaxf(xv.z, xv.w));
#pragma unroll
    for (int o = 16; o > 0; o >>= 1) m = fmaxf(m, __shfl_xor_sync(0xffffffffu, m, o));
    if (lane == 0) red[w] = m;
    __syncthreads();
    m = fmaxf(fmaxf(red[0], red[1]), fmaxf(red[2], red[3]));
    __syncthreads();

    float4 ev;
    ev.x = expf(xv.x - m); ev.y = expf(xv.y - m);
    ev.z = expf(xv.z - m); ev.w = expf(xv.w - m);
    float s = ev.x + ev.y + ev.z + ev.w;
#pragma unroll
    for (int o = 16; o > 0; o >>= 1) s += __shfl_xor_sync(0xffffffffu, s, o);
    if (lane == 0) red[w] = s;
    __syncthreads();
    s = red[0] + red[1] + red[2] + red[3];
    float inv = 1.0f / s;
    ev.x *= inv; ev.y *= inv; ev.z *= inv; ev.w *= inv;
    ((float4*)p)[tid] = ev;
}

// ------- V transpose: vt[nh][r*32+d][i] = v[((r*512+i)*4+n)*256 + h*32 + d] ------
__global__ __launch_bounds__(256) void transpose_v(
    const __half* __restrict__ v, __half* __restrict__ vt)
{
    __shared__ float sm[128][33];
    const int tid = threadIdx.x;
    const int i0 = (blockIdx.x >> 3) * 128;
    const int h = blockIdx.x & 7;
    const int r = blockIdx.y;
    const int n = blockIdx.z;

    const __half* base = v + (((size_t)r * 512 + i0) * 4 + n) * 256 + h * 32;
#pragma unroll
    for (int it = 0; it < 2; it++) {
        int idx = tid + it * 256;
        int row = idx >> 2, g = idx & 3;
        uint4 u = *(const uint4*)(base + (size_t)row * 1024 + g * 8);
        const __half2* hp = (const __half2*)&u;
#pragma unroll
        for (int c = 0; c < 4; c++) {
            float2 f = __half22float2(hp[c]);
            sm[row][g * 8 + c * 2 + 0] = f.x;
            sm[row][g * 8 + c * 2 + 1] = f.y;
        }
    }
    __syncthreads();
    __half* ob = vt + ((size_t)(h * 4 + n) * 2048 + r * 32) * 512 + i0;
#pragma unroll
    for (int it = 0; it < 2; it++) {
        int idx = tid + it * 256;
        int d = idx & 31, grp = idx >> 5, i8 = grp * 8;
        __half2 h0 = __float22half2_rn(make_float2(sm[i8 + 0][d], sm[i8 + 1][d]));
        __half2 h1 = __float22half2_rn(make_float2(sm[i8 + 2][d], sm[i8 + 3][d]));
        __half2 h2 = __float22half2_rn(make_float2(sm[i8 + 4][d], sm[i8 + 5][d]));
        __half2 h3 = __float22half2_rn(make_float2(sm[i8 + 6][d], sm[i8 + 7][d]));
        uint4 u;
        u.x = *(uint32_t*)&h0; u.y = *(uint32_t*)&h1;
        u.z = *(uint32_t*)&h2; u.w = *(uint32_t*)&h3;
        *(uint4*)(ob + (size_t)d * 512 + i8) = u;
    }
}

// ===== context: ctx[r,i,n,h,d] = sum_j P[h,n,i,j] vt[nh][r*32+d][j] ==============
__global__ __launch_bounds__(256) void context_gemm(
    const float* __restrict__ P, const __half* __restrict__ vt, __half* __restrict__ ctx)
{
    __shared__ __align__(16) char smA[2][TILE_BYTES];
    __shared__ __align__(16) char smB[2][TILE_BYTES];
    const int tid = threadIdx.x, warp = tid >> 5, lane = tid & 31;
    const int wm = (warp >> 2) * 64, wn = (warp & 3) * 32;
    const int i0 = blockIdx.x * 128;
    const int c0 = blockIdx.y * 128;      // over r*32+d (2048 wide)
    const int z = blockIdx.z, h = z >> 2, n = z & 3;
    const int nh = h * 4 + n;

    float acc[4][4][4];
#pragma unroll
    for (int fq = 0; fq < 4; fq++)
#pragma unroll
        for (int g = 0; g < 4; g++)
#pragma unroll
            for (int c = 0; c < 4; c++) acc[fq][g][c] = 0.f;

    const float* Ab = P + ((size_t)nh * 512 + i0) * 512;       // rows i, K = j
    const __half* Bb = vt + ((size_t)nh * 2048 + c0) * 512;    // rows c, K = j
    float4 pf[2][2]; uint4 dummyh[2];
    float4 dummyf[2][2]; uint4 pb[2];

    g2r<false>(Ab, 512, tid, pf, dummyh);
    g2r<true>(Bb, 512, tid, dummyf, pb);
    r2s<false>(smA[0], tid, pf, dummyh);
    r2s<true>(smB[0], tid, dummyf, pb);
    __syncthreads();

    uint32_t sA[2] = {smem_u32(smA[0]), smem_u32(smA[1])};
    uint32_t sB[2] = {smem_u32(smB[0]), smem_u32(smB[1])};

    const int NCH = 16;   // K = 512 / 32
    for (int ch = 0; ch < NCH; ch++) {
        if (ch + 1 < NCH) {
            g2r<false>(Ab + (ch + 1) * 32, 512, tid, pf, dummyh);
            g2r<true>(Bb + (ch + 1) * 32, 512, tid, dummyf, pb);
        }
        compute_chunk(sA[ch & 1], sB[ch & 1], wm, wn, lane, acc);
        if (ch + 1 < NCH) {
            r2s<false>(smA[(ch + 1) & 1], tid, pf, dummyh);
            r2s<true>(smB[(ch + 1) & 1], tid, dummyf, pb);
        }
        __syncthreads();
    }

    const int grp = lane >> 2, qid = lane & 3;
#pragma unroll
    for (int fq = 0; fq < 4; fq++)
#pragma unroll
        for (int rr = 0; rr < 2; rr++) {
            int i = i0 + wm + fq * 16 + grp + rr * 8;
#pragma unroll
            for (int g = 0; g < 4; g++) {
                int col = c0 + wn + g * 8 + qid * 2;
                int r = col >> 5, d = col & 31;
                float2 o;
                o.x = acc[fq][g][rr * 2 + 0];
                o.y = acc[fq][g][rr * 2 + 1];
                *(__half2*)(ctx + (((size_t)r * 512 + i) * 4 + n) * 256 + h * 32 + d) =
                    __float22half2_rn(o);
            }
        }
}

// --------------------------------- launch ---------------------------------------
extern "C" void kernel_launch(void* const* d_in, const int* in_sizes, int n_in,
                              void* d_out, int out_size) {
    const float* x   = (const float*)d_in[0];
    const int*   dst = (const int*)  d_in[1];
    const float* Wq  = (const float*)d_in[2];
    const float* bq  = (const float*)d_in[3];
    const float* Wk  = (const float*)d_in[4];
    const float* bk  = (const float*)d_in[5];
    const float* Wv  = (const float*)d_in[6];
    const float* bv  = (const float*)d_in[7];
    const float* Wo  = (const float*)d_in[8];
    const float* bo  = (const float*)d_in[9];
    const float* rel = (const float*)d_in[10];
    float* out = (float*)d_out;

    __half *q, *k, *v, *vt, *ctx;
    float* probs_fallback;
    unsigned char* bkt;
    cudaGetSymbolAddress((void**)&q,   gh_q);
    cudaGetSymbolAddress((void**)&k,   gh_k);
    cudaGetSymbolAddress((void**)&v,   gh_v);
    cudaGetSymbolAddress((void**)&vt,  gh_vt);
    cudaGetSymbolAddress((void**)&ctx, gh_ctx);
    cudaGetSymbolAddress((void**)&probs_fallback, g_probs);
    cudaGetSymbolAddress((void**)&bkt, g_bkt);

    float* probs = ((size_t)out_size >= OUT_ELEMS + PROB_ELEMS) ? (out + OUT_ELEMS)
                                                                : probs_fallback;

    const float scaleq = 0.022097086912079608f;  // D^-0.5 / sqrt(R)
    dim3 blk(256);

    bucket_kernel<<<(N_DIM * I_DIM * I_DIM) / 256, blk>>>(dst, bkt);

    proj_gemm<false, true><<<dim3(T_TOK / 128, E_DIM / 128), blk>>>(x, Wq, bq, q, scaleq);
    proj_gemm<false, true><<<dim3(T_TOK / 128, E_DIM / 128), blk>>>(x, Wk, bk, k, 1.0f);
    proj_gemm<false, true><<<dim3(T_TOK / 128, E_DIM / 128), blk>>>(x, Wv, bv, v, 1.0f);

    transpose_v<<<dim3(32, R_DIM, N_DIM), blk>>>(v, vt);

    logits_gemm<<<dim3(I_DIM / 128, I_DIM / 128, N_DIM * H_DIM), blk>>>(q, k, bkt, rel, probs);
    softmax_kernel<<<H_DIM * N_DIM * I_DIM, 128>>>(probs);
    context_gemm<<<dim3(I_DIM / 128, (R_DIM * D_DIM) / 128, N_DIM * H_DIM), blk>>>(probs, vt, ctx);

    proj_gemm<true, false><<<dim3(T_TOK / 128, E_DIM / 128), blk>>>(ctx, Wo, bo, out, 1.0f);
}

// round 6
// speedup vs baseline: 5.1863x; 1.4484x over previous
#include <cuda_runtime.h>
#include <cuda_fp16.h>
#include <math.h>
#include <stdint.h>

#define R_DIM 64
#define I_DIM 512
#define N_DIM 4
#define E_DIM 256
#define H_DIM 8
#define D_DIM 32
#define T_TOK (R_DIM * I_DIM * N_DIM)                 /* 131072 tokens */
#define OUT_ELEMS ((size_t)T_TOK * E_DIM)             /* 33554432 */
#define PROB_ELEMS ((size_t)H_DIM * N_DIM * I_DIM * I_DIM) /* 8388608 */

#define ROWB 80                    /* padded bytes per 32-half smem row */
#define TILE_BYTES (128 * ROWB)    /* 10240 */
#define STG_BYTES (2 * TILE_BYTES) /* A+B per stage: 20480 */
#define SMEM_GEMM (3 * STG_BYTES)  /* 61440 */

// ---------------- scratch (alloc-free rule: __device__ globals) ----------------
__device__ __half gh_x[T_TOK * E_DIM];
__device__ __half gh_w[4 * E_DIM * E_DIM];
__device__ __half gh_q[T_TOK * E_DIM];
__device__ __half gh_k[T_TOK * E_DIM];
__device__ __half gh_v[T_TOK * E_DIM];
__device__ __half gh_vt[T_TOK * E_DIM];   // V transposed: [nh][r*32+d][i], fp16
__device__ __half gh_ctx[T_TOK * E_DIM];
__device__ __half gh_pr[PROB_ELEMS];      // fp16 probs for context GEMM
__device__ float g_probs[PROB_ELEMS];     // fallback f32 probs
__device__ unsigned char g_bkt[N_DIM * I_DIM * I_DIM];

// ---------------- low-level helpers ---------------------------------------------
__device__ __forceinline__ uint32_t smem_u32(const void* p) {
    uint32_t a;
    asm("{ .reg .u64 t; cvta.to.shared.u64 t, %1; cvt.u32.u64 %0, t; }" : "=r"(a) : "l"(p));
    return a;
}
__device__ __forceinline__ void cp16(uint32_t saddr, const void* g) {
    asm volatile("cp.async.cg.shared.global [%0], [%1], 16;" :: "r"(saddr), "l"(g));
}
#define CP_COMMIT() asm volatile("cp.async.commit_group;" ::: "memory")
#define CP_WAIT1()  asm volatile("cp.async.wait_group 1;" ::: "memory")
__device__ __forceinline__ void ldsm4(uint32_t& r0, uint32_t& r1, uint32_t& r2, uint32_t& r3,
                                      uint32_t addr) {
    asm volatile("ldmatrix.sync.aligned.m8n8.x4.shared.b16 {%0,%1,%2,%3}, [%4];"
                 : "=r"(r0), "=r"(r1), "=r"(r2), "=r"(r3) : "r"(addr));
}
__device__ __forceinline__ void mma16816(float c[4], const uint32_t a[4], const uint32_t b[2]) {
    asm volatile(
        "mma.sync.aligned.m16n8k16.row.col.f32.f16.f16.f32 "
        "{%0,%1,%2,%3}, {%4,%5,%6,%7}, {%8,%9}, {%0,%1,%2,%3};"
        : "+f"(c[0]), "+f"(c[1]), "+f"(c[2]), "+f"(c[3])
        : "r"(a[0]), "r"(a[1]), "r"(a[2]), "r"(a[3]), "r"(b[0]), "r"(b[1]));
}

// 128 rows x 32 halves tile via cp.async (512 x 16B, 2 per thread)
__device__ __forceinline__ void load_tile(uint32_t sdst, const __half* base,
                                          size_t stride, int tid) {
#pragma unroll
    for (int it = 0; it < 2; it++) {
        int idx = tid + it * 256;
        int row = idx >> 2, g = idx & 3;
        cp16(sdst + row * ROWB + g * 16, base + (size_t)row * stride + g * 8);
    }
}

// --------- per-warp compute on one 32-deep K chunk: 12 LDSM.x4, 32 HMMA ---------
__device__ __forceinline__ void compute_chunk(uint32_t bufA, uint32_t bufB,
                                              int wm, int wn, int lane, float acc[4][4][4]) {
    uint32_t aoff = bufA + (uint32_t)((wm + (lane & 15)) * ROWB + ((lane >> 4) << 4));
    uint32_t boff = bufB + (uint32_t)((wn + ((lane >> 4) << 3) + (lane & 7)) * ROWB
                                      + (((lane >> 3) & 1) << 4));
#pragma unroll
    for (int ks = 0; ks < 2; ks++) {
        uint32_t a[4][4];
#pragma unroll
        for (int fq = 0; fq < 4; fq++)
            ldsm4(a[fq][0], a[fq][1], a[fq][2], a[fq][3], aoff + fq * (16 * ROWB) + ks * 32);
        uint32_t b[4][2];
#pragma unroll
        for (int p = 0; p < 2; p++) {
            uint32_t r0, r1, r2, r3;
            ldsm4(r0, r1, r2, r3, boff + p * (16 * ROWB) + ks * 32);
            b[p * 2][0] = r0; b[p * 2][1] = r1;
            b[p * 2 + 1][0] = r2; b[p * 2 + 1][1] = r3;
        }
#pragma unroll
        for (int fq = 0; fq < 4; fq++)
#pragma unroll
            for (int g = 0; g < 4; g++)
                mma16816(acc[fq][g], a[fq], b[g]);
    }
}

// 3-stage cp.async mainloop shared by all GEMMs. NCH >= 2.
__device__ __forceinline__ void gemm_main(
    const __half* Ab, size_t strideA, size_t chA,
    const __half* Bb, size_t strideB, size_t chB,
    int NCH, uint32_t sbase, int tid, int wm, int wn, int lane, float acc[4][4][4])
{
    load_tile(sbase, Ab, strideA, tid);
    load_tile(sbase + TILE_BYTES, Bb, strideB, tid);
    CP_COMMIT();
    load_tile(sbase + STG_BYTES, Ab + chA, strideA, tid);
    load_tile(sbase + STG_BYTES + TILE_BYTES, Bb + chB, strideB, tid);
    CP_COMMIT();

    int cs = 0, ls = 2;
    for (int ch = 0; ch < NCH; ch++) {
        CP_WAIT1();
        __syncthreads();
        if (ch + 2 < NCH) {
            uint32_t so = sbase + ls * STG_BYTES;
            load_tile(so, Ab + (size_t)(ch + 2) * chA, strideA, tid);
            load_tile(so + TILE_BYTES, Bb + (size_t)(ch + 2) * chB, strideB, tid);
        }
        CP_COMMIT();
        if (++ls == 3) ls = 0;
        compute_chunk(sbase + cs * STG_BYTES, sbase + cs * STG_BYTES + TILE_BYTES,
                      wm, wn, lane, acc);
        if (++cs == 3) cs = 0;
    }
}

// T5 bucketize (verified exact vs jnp.linspace/searchsorted in R2/R3)
__device__ __forceinline__ int bucket_of(int dist) {
    int ad = dist < 0 ? -dist : dist;
    float v = (float)ad;
    int lo = 0, hi = 62;
#pragma unroll
    for (int it = 0; it < 6; it++) {
        int mid = (lo + hi) >> 1;
        float b = (float)((50000.0 * (double)mid) / 62.0);
        if (b >= v) hi = mid; else lo = mid + 1;
    }
    return lo;
}
__global__ __launch_bounds__(256) void bucket_kernel(
    const int* __restrict__ dist, unsigned char* __restrict__ bkt) {
    int idx = blockIdx.x * 256 + threadIdx.x;
    bkt[idx] = (unsigned char)bucket_of(dist[idx]);
}

// ---------------- f32 -> f16 bulk convert (8 elems/thread) ----------------------
__global__ __launch_bounds__(256) void conv_f16(
    const float* __restrict__ src, __half* __restrict__ dst) {
    size_t idx = ((size_t)blockIdx.x * 256 + threadIdx.x) * 8;
    float4 a = *(const float4*)(src + idx);
    float4 b = *(const float4*)(src + idx + 4);
    __half2 h0 = __float22half2_rn(make_float2(a.x, a.y));
    __half2 h1 = __float22half2_rn(make_float2(a.z, a.w));
    __half2 h2 = __float22half2_rn(make_float2(b.x, b.y));
    __half2 h3 = __float22half2_rn(make_float2(b.z, b.w));
    uint4 u;
    u.x = *(uint32_t*)&h0; u.y = *(uint32_t*)&h1;
    u.z = *(uint32_t*)&h2; u.w = *(uint32_t*)&h3;
    *(uint4*)(dst + idx) = u;
}

// ==================== projection: C[t,f] = (A·W^T + b)*scale ====================
template<bool O16>
__global__ __launch_bounds__(256, 2) void proj_gemm(
    const __half* __restrict__ A, const __half* __restrict__ W,
    const float* __restrict__ bias, void* __restrict__ C, float scale)
{
    extern __shared__ __align__(16) char smem[];
    const int tid = threadIdx.x, warp = tid >> 5, lane = tid & 31;
    const int wm = (warp >> 2) * 64, wn = (warp & 3) * 32;
    const int t0 = blockIdx.x * 128, f0 = blockIdx.y * 128;

    float acc[4][4][4];
#pragma unroll
    for (int fq = 0; fq < 4; fq++)
#pragma unroll
        for (int g = 0; g < 4; g++)
#pragma unroll
            for (int c = 0; c < 4; c++) acc[fq][g][c] = 0.f;

    gemm_main(A + (size_t)t0 * E_DIM, E_DIM, 32,
              W + (size_t)f0 * E_DIM, E_DIM, 32,
              E_DIM / 32, smem_u32(smem), tid, wm, wn, lane, acc);

    const int grp = lane >> 2, qid = lane & 3;
#pragma unroll
    for (int fq = 0; fq < 4; fq++)
#pragma unroll
        for (int rr = 0; rr < 2; rr++) {
            int i = t0 + wm + fq * 16 + grp + rr * 8;
#pragma unroll
            for (int g = 0; g < 4; g++) {
                int col = f0 + wn + g * 8 + qid * 2;
                float2 o;
                o.x = (acc[fq][g][rr * 2 + 0] + bias[col + 0]) * scale;
                o.y = (acc[fq][g][rr * 2 + 1] + bias[col + 1]) * scale;
                if (O16) {
                    *(__half2*)((__half*)C + (size_t)i * E_DIM + col) = __float22half2_rn(o);
                } else {
                    *(float2*)((float*)C + (size_t)i * E_DIM + col) = o;
                }
            }
        }
}

// =========== logits: out[h,n,i,j] = sum_{r,d} q·k + rel[bucket[n,i,j],h] =========
__global__ __launch_bounds__(256, 2) void logits_gemm(
    const __half* __restrict__ q, const __half* __restrict__ k,
    const unsigned char* __restrict__ bkt, const float* __restrict__ rel,
    float* __restrict__ out)
{
    extern __shared__ __align__(16) char smem[];
    const int tid = threadIdx.x, warp = tid >> 5, lane = tid & 31;
    const int wm = (warp >> 2) * 64, wn = (warp & 3) * 32;
    const int i0 = blockIdx.x * 128, j0 = blockIdx.y * 128;
    const int z = blockIdx.z, h = z >> 2, n = z & 3;

    float acc[4][4][4];
#pragma unroll
    for (int fq = 0; fq < 4; fq++)
#pragma unroll
        for (int g = 0; g < 4; g++)
#pragma unroll
            for (int c = 0; c < 4; c++) acc[fq][g][c] = 0.f;

    // token layout [t][f]: t=(r*512+i)*4+n, f=h*32+d; chunk ch = r
    gemm_main(q + ((size_t)i0 * 4 + n) * 256 + h * 32, 1024, 524288,
              k + ((size_t)j0 * 4 + n) * 256 + h * 32, 1024, 524288,
              64, smem_u32(smem), tid, wm, wn, lane, acc);

    const int grp = lane >> 2, qid = lane & 3;
#pragma unroll
    for (int fq = 0; fq < 4; fq++)
#pragma unroll
        for (int rr = 0; rr < 2; rr++) {
            int i = i0 + wm + fq * 16 + grp + rr * 8;
            const unsigned char* brow = bkt + ((size_t)n * I_DIM + i) * I_DIM;
            float* orow = out + ((size_t)(h * 4 + n) * I_DIM + i) * I_DIM;
#pragma unroll
            for (int g = 0; g < 4; g++) {
                int j = j0 + wn + g * 8 + qid * 2;
                float2 o;
                o.x = acc[fq][g][rr * 2 + 0] + rel[brow[j + 0] * H_DIM + h];
                o.y = acc[fq][g][rr * 2 + 1] + rel[brow[j + 1] * H_DIM + h];
                *(float2*)(orow + j) = o;
            }
        }
}

// ------------- softmax over last dim (512), writes f32 + f16 copies -------------
__global__ __launch_bounds__(128) void softmax_kernel(
    float* __restrict__ P, __half* __restrict__ Ph) {
    float* p = P + (size_t)blockIdx.x * 512;
    __half* ph = Ph + (size_t)blockIdx.x * 512;
    const int tid = threadIdx.x;
    const int w = tid >> 5, lane = tid & 31;
    __shared__ float red[4];

    float4 xv = ((float4*)p)[tid];
    float m = fmaxf(fmaxf(xv.x, xv.y), fmaxf(xv.z, xv.w));
#pragma unroll
    for (int o = 16; o > 0; o >>= 1) m = fmaxf(m, __shfl_xor_sync(0xffffffffu, m, o));
    if (lane == 0) red[w] = m;
    __syncthreads();
    m = fmaxf(fmaxf(red[0], red[1]), fmaxf(red[2], red[3]));
    __syncthreads();

    float4 ev;
    ev.x = expf(xv.x - m); ev.y = expf(xv.y - m);
    ev.z = expf(xv.z - m); ev.w = expf(xv.w - m);
    float s = ev.x + ev.y + ev.z + ev.w;
#pragma unroll
    for (int o = 16; o > 0; o >>= 1) s += __shfl_xor_sync(0xffffffffu, s, o);
    if (lane == 0) red[w] = s;
    __syncthreads();
    s = red[0] + red[1] + red[2] + red[3];
    float inv = 1.0f / s;
    ev.x *= inv; ev.y *= inv; ev.z *= inv; ev.w *= inv;
    ((float4*)p)[tid] = ev;
    __half2 h0 = __float22half2_rn(make_float2(ev.x, ev.y));
    __half2 h1 = __float22half2_rn(make_float2(ev.z, ev.w));
    uint2 u; u.x = *(uint32_t*)&h0; u.y = *(uint32_t*)&h1;
    *(uint2*)(ph + tid * 4) = u;
}

// ------- V transpose: vt[nh][r*32+d][i] = v[((r*512+i)*4+n)*256 + h*32 + d] ------
__global__ __launch_bounds__(256) void transpose_v(
    const __half* __restrict__ v, __half* __restrict__ vt)
{
    __shared__ float sm[128][33];
    const int tid = threadIdx.x;
    const int i0 = (blockIdx.x >> 3) * 128;
    const int h = blockIdx.x & 7;
    const int r = blockIdx.y;
    const int n = blockIdx.z;

    const __half* base = v + (((size_t)r * 512 + i0) * 4 + n) * 256 + h * 32;
#pragma unroll
    for (int it = 0; it < 2; it++) {
        int idx = tid + it * 256;
        int row = idx >> 2, g = idx & 3;
        uint4 u = *(const uint4*)(base + (size_t)row * 1024 + g * 8);
        const __half2* hp = (const __half2*)&u;
#pragma unroll
        for (int c = 0; c < 4; c++) {
            float2 f = __half22float2(hp[c]);
            sm[row][g * 8 + c * 2 + 0] = f.x;
            sm[row][g * 8 + c * 2 + 1] = f.y;
        }
    }
    __syncthreads();
    __half* ob = vt + ((size_t)(h * 4 + n) * 2048 + r * 32) * 512 + i0;
#pragma unroll
    for (int it = 0; it < 2; it++) {
        int idx = tid + it * 256;
        int d = idx & 31, grp = idx >> 5, i8 = grp * 8;
        __half2 h0 = __float22half2_rn(make_float2(sm[i8 + 0][d], sm[i8 + 1][d]));
        __half2 h1 = __float22half2_rn(make_float2(sm[i8 + 2][d], sm[i8 + 3][d]));
        __half2 h2 = __float22half2_rn(make_float2(sm[i8 + 4][d], sm[i8 + 5][d]));
        __half2 h3 = __float22half2_rn(make_float2(sm[i8 + 6][d], sm[i8 + 7][d]));
        uint4 u;
        u.x = *(uint32_t*)&h0; u.y = *(uint32_t*)&h1;
        u.z = *(uint32_t*)&h2; u.w = *(uint32_t*)&h3;
        *(uint4*)(ob + (size_t)d * 512 + i8) = u;
    }
}

// ===== context: ctx[r,i,n,h,d] = sum_j P[h,n,i,j] vt[nh][r*32+d][j] ==============
__global__ __launch_bounds__(256, 2) void context_gemm(
    const __half* __restrict__ Ph, const __half* __restrict__ vt,
    __half* __restrict__ ctx)
{
    extern __shared__ __align__(16) char smem[];
    const int tid = threadIdx.x, warp = tid >> 5, lane = tid & 31;
    const int wm = (warp >> 2) * 64, wn = (warp & 3) * 32;
    const int i0 = blockIdx.x * 128;
    const int c0 = blockIdx.y * 128;      // over r*32+d (2048 wide)
    const int z = blockIdx.z, h = z >> 2, n = z & 3;
    const int nh = h * 4 + n;

    float acc[4][4][4];
#pragma unroll
    for (int fq = 0; fq < 4; fq++)
#pragma unroll
        for (int g = 0; g < 4; g++)
#pragma unroll
            for (int c = 0; c < 4; c++) acc[fq][g][c] = 0.f;

    gemm_main(Ph + ((size_t)nh * 512 + i0) * 512, 512, 32,
              vt + ((size_t)nh * 2048 + c0) * 512, 512, 32,
              16, smem_u32(smem), tid, wm, wn, lane, acc);

    const int grp = lane >> 2, qid = lane & 3;
#pragma unroll
    for (int fq = 0; fq < 4; fq++)
#pragma unroll
        for (int rr = 0; rr < 2; rr++) {
            int i = i0 + wm + fq * 16 + grp + rr * 8;
#pragma unroll
            for (int g = 0; g < 4; g++) {
                int col = c0 + wn + g * 8 + qid * 2;
                int r = col >> 5, d = col & 31;
                float2 o;
                o.x = acc[fq][g][rr * 2 + 0];
                o.y = acc[fq][g][rr * 2 + 1];
                *(__half2*)(ctx + (((size_t)r * 512 + i) * 4 + n) * 256 + h * 32 + d) =
                    __float22half2_rn(o);
            }
        }
}

// --------------------------------- launch ---------------------------------------
extern "C" void kernel_launch(void* const* d_in, const int* in_sizes, int n_in,
                              void* d_out, int out_size) {
    const float* x   = (const float*)d_in[0];
    const int*   dst = (const int*)  d_in[1];
    const float* Wq  = (const float*)d_in[2];
    const float* bq  = (const float*)d_in[3];
    const float* Wk  = (const float*)d_in[4];
    const float* bk  = (const float*)d_in[5];
    const float* Wv  = (const float*)d_in[6];
    const float* bv  = (const float*)d_in[7];
    const float* Wo  = (const float*)d_in[8];
    const float* bo  = (const float*)d_in[9];
    const float* rel = (const float*)d_in[10];
    float* out = (float*)d_out;

    __half *xh, *wh, *q, *k, *v, *vt, *ctx, *ph;
    float* probs_fallback;
    unsigned char* bkt;
    cudaGetSymbolAddress((void**)&xh,  gh_x);
    cudaGetSymbolAddress((void**)&wh,  gh_w);
    cudaGetSymbolAddress((void**)&q,   gh_q);
    cudaGetSymbolAddress((void**)&k,   gh_k);
    cudaGetSymbolAddress((void**)&v,   gh_v);
    cudaGetSymbolAddress((void**)&vt,  gh_vt);
    cudaGetSymbolAddress((void**)&ctx, gh_ctx);
    cudaGetSymbolAddress((void**)&ph,  gh_pr);
    cudaGetSymbolAddress((void**)&probs_fallback, g_probs);
    cudaGetSymbolAddress((void**)&bkt, g_bkt);

    float* probs = ((size_t)out_size >= OUT_ELEMS + PROB_ELEMS) ? (out + OUT_ELEMS)
                                                                : probs_fallback;

    cudaFuncSetAttribute(proj_gemm<true>,  cudaFuncAttributeMaxDynamicSharedMemorySize, SMEM_GEMM);
    cudaFuncSetAttribute(proj_gemm<false>, cudaFuncAttributeMaxDynamicSharedMemorySize, SMEM_GEMM);
    cudaFuncSetAttribute(logits_gemm,      cudaFuncAttributeMaxDynamicSharedMemorySize, SMEM_GEMM);
    cudaFuncSetAttribute(context_gemm,     cudaFuncAttributeMaxDynamicSharedMemorySize, SMEM_GEMM);

    const float scaleq = 0.022097086912079608f;  // D^-0.5 / sqrt(R)
    dim3 blk(256);

    bucket_kernel<<<(N_DIM * I_DIM * I_DIM) / 256, blk>>>(dst, bkt);

    // fp16 pre-conversion: x (33.5M) and the four 256x256 weights
    conv_f16<<<(int)(OUT_ELEMS / (256 * 8)), blk>>>(x,  xh);
    conv_f16<<<E_DIM * E_DIM / (256 * 8), blk>>>(Wq, wh + 0 * E_DIM * E_DIM);
    conv_f16<<<E_DIM * E_DIM / (256 * 8), blk>>>(Wk, wh + 1 * E_DIM * E_DIM);
    conv_f16<<<E_DIM * E_DIM / (256 * 8), blk>>>(Wv, wh + 2 * E_DIM * E_DIM);
    conv_f16<<<E_DIM * E_DIM / (256 * 8), blk>>>(Wo, wh + 3 * E_DIM * E_DIM);

    dim3 pgrid(T_TOK / 128, E_DIM / 128);
    proj_gemm<true><<<pgrid, blk, SMEM_GEMM>>>(xh, wh + 0 * E_DIM * E_DIM, bq, q, scaleq);
    proj_gemm<true><<<pgrid, blk, SMEM_GEMM>>>(xh, wh + 1 * E_DIM * E_DIM, bk, k, 1.0f);
    proj_gemm<true><<<pgrid, blk, SMEM_GEMM>>>(xh, wh + 2 * E_DIM * E_DIM, bv, v, 1.0f);

    transpose_v<<<dim3(32, R_DIM, N_DIM), blk>>>(v, vt);

    logits_gemm<<<dim3(I_DIM / 128, I_DIM / 128, N_DIM * H_DIM), blk, SMEM_GEMM>>>(
        q, k, bkt, rel, probs);
    softmax_kernel<<<H_DIM * N_DIM * I_DIM, 128>>>(probs, ph);
    context_gemm<<<dim3(I_DIM / 128, (R_DIM * D_DIM) / 128, N_DIM * H_DIM), blk, SMEM_GEMM>>>(
        ph, vt, ctx);

    proj_gemm<false><<<pgrid, blk, SMEM_GEMM>>>(ctx, wh + 3 * E_DIM * E_DIM, bo, out, 1.0f);
}

// round 8
// speedup vs baseline: 5.5283x; 1.0659x over previous
#include <cuda_runtime.h>
#include <cuda_fp16.h>
#include <math.h>
#include <stdint.h>

#define R_DIM 64
#define I_DIM 512
#define N_DIM 4
#define E_DIM 256
#define H_DIM 8
#define D_DIM 32
#define T_TOK (R_DIM * I_DIM * N_DIM)                 /* 131072 tokens */
#define OUT_ELEMS ((size_t)T_TOK * E_DIM)             /* 33554432 */
#define PROB_ELEMS ((size_t)H_DIM * N_DIM * I_DIM * I_DIM) /* 8388608 */

#define ROWB 80                    /* padded bytes per 32-half smem row (16B-aligned!) */
#define TILE_BYTES (128 * ROWB)    /* 10240 */
#define STG_BYTES (2 * TILE_BYTES) /* A+B per stage: 20480 */
#define NSTG 4
#define SMEM_GEMM (NSTG * STG_BYTES)  /* 81920 */

// ---------------- scratch (alloc-free rule: __device__ globals) ----------------
__device__ __half gh_x[T_TOK * E_DIM];
__device__ __half gh_w[4 * E_DIM * E_DIM];
__device__ __half gh_q[T_TOK * E_DIM];
__device__ __half gh_k[T_TOK * E_DIM];
__device__ __half gh_v[T_TOK * E_DIM];
__device__ __half gh_ctx[T_TOK * E_DIM];
__device__ __half gh_pr[PROB_ELEMS];      // fp16 probs for context GEMM
__device__ float g_probs[PROB_ELEMS];     // fallback f32 probs
__device__ unsigned char g_bkt[N_DIM * I_DIM * I_DIM];

// ---------------- low-level helpers ---------------------------------------------
__device__ __forceinline__ uint32_t smem_u32(const void* p) {
    uint32_t a;
    asm("{ .reg .u64 t; cvta.to.shared.u64 t, %1; cvt.u32.u64 %0, t; }" : "=r"(a) : "l"(p));
    return a;
}
__device__ __forceinline__ void cp16(uint32_t saddr, const void* g) {
    asm volatile("cp.async.cg.shared.global [%0], [%1], 16;" :: "r"(saddr), "l"(g));
}
#define CP_COMMIT() asm volatile("cp.async.commit_group;" ::: "memory")
#define CP_WAIT2()  asm volatile("cp.async.wait_group 2;" ::: "memory")
__device__ __forceinline__ void ldsm4(uint32_t& r0, uint32_t& r1, uint32_t& r2, uint32_t& r3,
                                      uint32_t addr) {
    asm volatile("ldmatrix.sync.aligned.m8n8.x4.shared.b16 {%0,%1,%2,%3}, [%4];"
                 : "=r"(r0), "=r"(r1), "=r"(r2), "=r"(r3) : "r"(addr));
}
__device__ __forceinline__ void ldsm4t(uint32_t& r0, uint32_t& r1, uint32_t& r2, uint32_t& r3,
                                       uint32_t addr) {
    asm volatile("ldmatrix.sync.aligned.m8n8.x4.trans.shared.b16 {%0,%1,%2,%3}, [%4];"
                 : "=r"(r0), "=r"(r1), "=r"(r2), "=r"(r3) : "r"(addr));
}
__device__ __forceinline__ void mma16816(float c[4], const uint32_t a[4], const uint32_t b[2]) {
    asm volatile(
        "mma.sync.aligned.m16n8k16.row.col.f32.f16.f16.f32 "
        "{%0,%1,%2,%3}, {%4,%5,%6,%7}, {%8,%9}, {%0,%1,%2,%3};"
        : "+f"(c[0]), "+f"(c[1]), "+f"(c[2]), "+f"(c[3])
        : "r"(a[0]), "r"(a[1]), "r"(a[2]), "r"(a[3]), "r"(b[0]), "r"(b[1]));
}

// Unified tile loader: 128 rows x 32 halves via cp.async.
// addr(row) = base + (row>>5)*grpStride + (row&31)*rowStride  (strides in halves)
__device__ __forceinline__ void load_tile(uint32_t sdst, const __half* base,
                                          size_t rowStride, size_t grpStride, int tid) {
#pragma unroll
    for (int it = 0; it < 2; it++) {
        int idx = tid + it * 256;
        int row = idx >> 2, g = idx & 3;
        const __half* src = base + (size_t)(row >> 5) * grpStride
                                 + (size_t)(row & 31) * rowStride + g * 8;
        cp16(sdst + row * ROWB + g * 16, src);
    }
}

// --------- per-warp compute on one 32-deep K chunk ------------------------------
// BTRANS=false: B tile is [n rows][k halves] (non-trans ldsm)
// BTRANS=true : B tile is [k rows][n halves] (trans ldsm); rows grouped 32/r-grp
template<bool BTRANS>
__device__ __forceinline__ void compute_chunk(uint32_t bufA, uint32_t bufB,
                                              int wm, int wn, int lane, float acc[4][4][4]) {
    uint32_t aoff = bufA + (uint32_t)((wm + (lane & 15)) * ROWB + ((lane >> 4) << 4));
    uint32_t boff;
    if (BTRANS) {
        boff = bufB + (uint32_t)(((wn >> 5) * 32 + (lane & 15)) * ROWB
                                 + ((lane >> 4) << 4));
    } else {
        boff = bufB + (uint32_t)((wn + ((lane >> 4) << 3) + (lane & 7)) * ROWB
                                 + (((lane >> 3) & 1) << 4));
    }
#pragma unroll
    for (int ks = 0; ks < 2; ks++) {
        uint32_t a[4][4];
#pragma unroll
        for (int fq = 0; fq < 4; fq++)
            ldsm4(a[fq][0], a[fq][1], a[fq][2], a[fq][3], aoff + fq * (16 * ROWB) + ks * 32);
        uint32_t b[4][2];
        if (BTRANS) {
#pragma unroll
            for (int p = 0; p < 2; p++) {
                uint32_t r0, r1, r2, r3;
                ldsm4t(r0, r1, r2, r3, boff + ks * (16 * ROWB) + p * 32);
                b[p * 2][0] = r0; b[p * 2][1] = r1;
                b[p * 2 + 1][0] = r2; b[p * 2 + 1][1] = r3;
            }
        } else {
#pragma unroll
            for (int p = 0; p < 2; p++) {
                uint32_t r0, r1, r2, r3;
                ldsm4(r0, r1, r2, r3, boff + p * (16 * ROWB) + ks * 32);
                b[p * 2][0] = r0; b[p * 2][1] = r1;
                b[p * 2 + 1][0] = r2; b[p * 2 + 1][1] = r3;
            }
        }
#pragma unroll
        for (int fq = 0; fq < 4; fq++)
#pragma unroll
            for (int g = 0; g < 4; g++)
                mma16816(acc[fq][g], a[fq], b[g]);
    }
}

// 4-stage cp.async mainloop shared by all GEMMs. NCH >= 3.
template<bool BTRANS>
__device__ __forceinline__ void gemm_main(
    const __half* Ab, size_t rsA, size_t gsA, size_t chA,
    const __half* Bb, size_t rsB, size_t gsB, size_t chB,
    int NCH, uint32_t sbase, int tid, int wm, int wn, int lane, float acc[4][4][4])
{
#pragma unroll
    for (int s = 0; s < NSTG - 1; s++) {
        load_tile(sbase + s * STG_BYTES, Ab + (size_t)s * chA, rsA, gsA, tid);
        load_tile(sbase + s * STG_BYTES + TILE_BYTES, Bb + (size_t)s * chB, rsB, gsB, tid);
        CP_COMMIT();
    }
    int cs = 0, ls = NSTG - 1;
    for (int ch = 0; ch < NCH; ch++) {
        CP_WAIT2();
        __syncthreads();
        if (ch + NSTG - 1 < NCH) {
            uint32_t so = sbase + ls * STG_BYTES;
            load_tile(so, Ab + (size_t)(ch + NSTG - 1) * chA, rsA, gsA, tid);
            load_tile(so + TILE_BYTES, Bb + (size_t)(ch + NSTG - 1) * chB, rsB, gsB, tid);
        }
        CP_COMMIT();
        if (++ls == NSTG) ls = 0;
        compute_chunk<BTRANS>(sbase + cs * STG_BYTES, sbase + cs * STG_BYTES + TILE_BYTES,
                              wm, wn, lane, acc);
        if (++cs == NSTG) cs = 0;
    }
}

// T5 bucketize (verified exact vs jnp.linspace/searchsorted in R2/R3)
__device__ __forceinline__ int bucket_of(int dist) {
    int ad = dist < 0 ? -dist : dist;
    float v = (float)ad;
    int lo = 0, hi = 62;
#pragma unroll
    for (int it = 0; it < 6; it++) {
        int mid = (lo + hi) >> 1;
        float b = (float)((50000.0 * (double)mid) / 62.0);
        if (b >= v) hi = mid; else lo = mid + 1;
    }
    return lo;
}
__global__ __launch_bounds__(256) void bucket_kernel(
    const int* __restrict__ dist, unsigned char* __restrict__ bkt) {
    int idx = blockIdx.x * 256 + threadIdx.x;
    bkt[idx] = (unsigned char)bucket_of(dist[idx]);
}

// ---------------- f32 -> f16 bulk converts --------------------------------------
__global__ __launch_bounds__(256) void conv_f16(
    const float* __restrict__ src, __half* __restrict__ dst) {
    size_t idx = ((size_t)blockIdx.x * 256 + threadIdx.x) * 8;
    float4 a = *(const float4*)(src + idx);
    float4 b = *(const float4*)(src + idx + 4);
    __half2 h0 = __float22half2_rn(make_float2(a.x, a.y));
    __half2 h1 = __float22half2_rn(make_float2(a.z, a.w));
    __half2 h2 = __float22half2_rn(make_float2(b.x, b.y));
    __half2 h3 = __float22half2_rn(make_float2(b.z, b.w));
    uint4 u;
    u.x = *(uint32_t*)&h0; u.y = *(uint32_t*)&h1;
    u.z = *(uint32_t*)&h2; u.w = *(uint32_t*)&h3;
    *(uint4*)(dst + idx) = u;
}
__global__ __launch_bounds__(256) void conv_w4(
    const float* __restrict__ w0, const float* __restrict__ w1,
    const float* __restrict__ w2, const float* __restrict__ w3,
    __half* __restrict__ dst) {
    const float* src = (blockIdx.y == 0) ? w0 : (blockIdx.y == 1) ? w1
                      : (blockIdx.y == 2) ? w2 : w3;
    size_t idx = ((size_t)blockIdx.x * 256 + threadIdx.x) * 8;
    float4 a = *(const float4*)(src + idx);
    float4 b = *(const float4*)(src + idx + 4);
    __half2 h0 = __float22half2_rn(make_float2(a.x, a.y));
    __half2 h1 = __float22half2_rn(make_float2(a.z, a.w));
    __half2 h2 = __float22half2_rn(make_float2(b.x, b.y));
    __half2 h3 = __float22half2_rn(make_float2(b.z, b.w));
    uint4 u;
    u.x = *(uint32_t*)&h0; u.y = *(uint32_t*)&h1;
    u.z = *(uint32_t*)&h2; u.w = *(uint32_t*)&h3;
    *(uint4*)(dst + (size_t)blockIdx.y * E_DIM * E_DIM + idx) = u;
}

// ==================== projection: C[t,f] = (A·W^T + b)*scale ====================
template<bool O16>
__global__ __launch_bounds__(256, 2) void proj_gemm(
    const __half* __restrict__ A, const __half* __restrict__ W,
    const float* __restrict__ bias, void* __restrict__ C, float scale)
{
    extern __shared__ __align__(16) char smem[];
    const int tid = threadIdx.x, warp = tid >> 5, lane = tid & 31;
    const int wm = (warp >> 2) * 64, wn = (warp & 3) * 32;
    const int t0 = blockIdx.x * 128, f0 = blockIdx.y * 128;

    float acc[4][4][4];
#pragma unroll
    for (int fq = 0; fq < 4; fq++)
#pragma unroll
        for (int g = 0; g < 4; g++)
#pragma unroll
            for (int c = 0; c < 4; c++) acc[fq][g][c] = 0.f;

    gemm_main<false>(A + (size_t)t0 * E_DIM, E_DIM, 32 * E_DIM, 32,
                     W + (size_t)f0 * E_DIM, E_DIM, 32 * E_DIM, 32,
                     E_DIM / 32, smem_u32(smem), tid, wm, wn, lane, acc);

    const int grp = lane >> 2, qid = lane & 3;
#pragma unroll
    for (int fq = 0; fq < 4; fq++)
#pragma unroll
        for (int rr = 0; rr < 2; rr++) {
            int i = t0 + wm + fq * 16 + grp + rr * 8;
#pragma unroll
            for (int g = 0; g < 4; g++) {
                int col = f0 + wn + g * 8 + qid * 2;
                float2 o;
                o.x = (acc[fq][g][rr * 2 + 0] + bias[col + 0]) * scale;
                o.y = (acc[fq][g][rr * 2 + 1] + bias[col + 1]) * scale;
                if (O16) {
                    *(__half2*)((__half*)C + (size_t)i * E_DIM + col) = __float22half2_rn(o);
                } else {
                    *(float2*)((float*)C + (size_t)i * E_DIM + col) = o;
                }
            }
        }
}

// =========== logits: out[h,n,i,j] = sum_{r,d} q·k + rel[bucket[n,i,j],h] =========
__global__ __launch_bounds__(256, 2) void logits_gemm(
    const __half* __restrict__ q, const __half* __restrict__ k,
    const unsigned char* __restrict__ bkt, const float* __restrict__ rel,
    float* __restrict__ out)
{
    extern __shared__ __align__(16) char smem[];
    const int tid = threadIdx.x, warp = tid >> 5, lane = tid & 31;
    const int wm = (warp >> 2) * 64, wn = (warp & 3) * 32;
    const int i0 = blockIdx.x * 128, j0 = blockIdx.y * 128;
    const int z = blockIdx.z, h = z >> 2, n = z & 3;

    float acc[4][4][4];
#pragma unroll
    for (int fq = 0; fq < 4; fq++)
#pragma unroll
        for (int g = 0; g < 4; g++)
#pragma unroll
            for (int c = 0; c < 4; c++) acc[fq][g][c] = 0.f;

    // token layout [t][f]: t=(r*512+i)*4+n, f=h*32+d; chunk ch = r
    gemm_main<false>(q + ((size_t)i0 * 4 + n) * 256 + h * 32, 1024, 32 * 1024, 524288,
                     k + ((size_t)j0 * 4 + n) * 256 + h * 32, 1024, 32 * 1024, 524288,
                     64, smem_u32(smem), tid, wm, wn, lane, acc);

    const int grp = lane >> 2, qid = lane & 3;
#pragma unroll
    for (int fq = 0; fq < 4; fq++)
#pragma unroll
        for (int rr = 0; rr < 2; rr++) {
            int i = i0 + wm + fq * 16 + grp + rr * 8;
            const unsigned char* brow = bkt + ((size_t)n * I_DIM + i) * I_DIM;
            float* orow = out + ((size_t)(h * 4 + n) * I_DIM + i) * I_DIM;
#pragma unroll
            for (int g = 0; g < 4; g++) {
                int j = j0 + wn + g * 8 + qid * 2;
                float2 o;
                o.x = acc[fq][g][rr * 2 + 0] + rel[brow[j + 0] * H_DIM + h];
                o.y = acc[fq][g][rr * 2 + 1] + rel[brow[j + 1] * H_DIM + h];
                *(float2*)(orow + j) = o;
            }
        }
}

// --------- softmax over last dim (512): 1 warp/row, 8 rows/block, no smem -------
__global__ __launch_bounds__(256) void softmax_kernel(
    float* __restrict__ P, __half* __restrict__ Ph) {
    const size_t row = (size_t)blockIdx.x * 8 + (threadIdx.x >> 5);
    const int lane = threadIdx.x & 31;
    float* p = P + row * 512;
    __half* ph = Ph + row * 512;

    float4 xv[4];
#pragma unroll
    for (int it = 0; it < 4; it++) xv[it] = ((float4*)p)[lane + it * 32];

    float m = -1e30f;
#pragma unroll
    for (int it = 0; it < 4; it++)
        m = fmaxf(m, fmaxf(fmaxf(xv[it].x, xv[it].y), fmaxf(xv[it].z, xv[it].w)));
#pragma unroll
    for (int o = 16; o > 0; o >>= 1) m = fmaxf(m, __shfl_xor_sync(0xffffffffu, m, o));

    float s = 0.f;
#pragma unroll
    for (int it = 0; it < 4; it++) {
        xv[it].x = expf(xv[it].x - m); xv[it].y = expf(xv[it].y - m);
        xv[it].z = expf(xv[it].z - m); xv[it].w = expf(xv[it].w - m);
        s += xv[it].x + xv[it].y + xv[it].z + xv[it].w;
    }
#pragma unroll
    for (int o = 16; o > 0; o >>= 1) s += __shfl_xor_sync(0xffffffffu, s, o);
    float inv = 1.0f / s;

#pragma unroll
    for (int it = 0; it < 4; it++) {
        xv[it].x *= inv; xv[it].y *= inv; xv[it].z *= inv; xv[it].w *= inv;
        ((float4*)p)[lane + it * 32] = xv[it];
        __half2 h0 = __float22half2_rn(make_float2(xv[it].x, xv[it].y));
        __half2 h1 = __float22half2_rn(make_float2(xv[it].z, xv[it].w));
        uint2 u; u.x = *(uint32_t*)&h0; u.y = *(uint32_t*)&h1;
        *(uint2*)(ph + (lane + it * 32) * 4) = u;
    }
}

// ===== context: ctx[r,i,n,h,d] = sum_j P[h,n,i,j] v[r,j,n,h,d]  (trans-B) ========
__global__ __launch_bounds__(256, 2) void context_gemm(
    const __half* __restrict__ Ph, const __half* __restrict__ v,
    __half* __restrict__ ctx)
{
    extern __shared__ __align__(16) char smem[];
    const int tid = threadIdx.x, warp = tid >> 5, lane = tid & 31;
    const int wm = (warp >> 2) * 64, wn = (warp & 3) * 32;
    const int i0 = blockIdx.x * 128;
    const int c0 = blockIdx.y * 128;      // over r*32+d (2048 wide)
    const int r0 = c0 >> 5;               // 4 r values per tile
    const int z = blockIdx.z, h = z >> 2, n = z & 3;
    const int nh = h * 4 + n;

    float acc[4][4][4];
#pragma unroll
    for (int fq = 0; fq < 4; fq++)
#pragma unroll
        for (int g = 0; g < 4; g++)
#pragma unroll
            for (int c = 0; c < 4; c++) acc[fq][g][c] = 0.f;

    // B tile rows: (rr*32 + jj) -> v[(((r0+rr)*512 + jch + jj)*4 + n)*256 + h*32 + d]
    // rowStride (jj) = 1024 halves, grpStride (rr) = 512*1024, chunk (j+=32) = 32*1024
    gemm_main<true>(Ph + ((size_t)nh * 512 + i0) * 512, 512, 32 * 512, 32,
                    v + ((size_t)r0 * 512 * 4 + n) * 256 + h * 32, 1024, 524288, 32768,
                    16, smem_u32(smem), tid, wm, wn, lane, acc);

    const int grp = lane >> 2, qid = lane & 3;
#pragma unroll
    for (int fq = 0; fq < 4; fq++)
#pragma unroll
        for (int rr = 0; rr < 2; rr++) {
            int i = i0 + wm + fq * 16 + grp + rr * 8;
#pragma unroll
            for (int g = 0; g < 4; g++) {
                int col = c0 + wn + g * 8 + qid * 2;
                int r = col >> 5, d = col & 31;
                float2 o;
                o.x = acc[fq][g][rr * 2 + 0];
                o.y = acc[fq][g][rr * 2 + 1];
                *(__half2*)(ctx + (((size_t)r * 512 + i) * 4 + n) * 256 + h * 32 + d) =
                    __float22half2_rn(o);
            }
        }
}

// --------------------------------- launch ---------------------------------------
extern "C" void kernel_launch(void* const* d_in, const int* in_sizes, int n_in,
                              void* d_out, int out_size) {
    const float* x   = (const float*)d_in[0];
    const int*   dst = (const int*)  d_in[1];
    const float* Wq  = (const float*)d_in[2];
    const float* bq  = (const float*)d_in[3];
    const float* Wk  = (const float*)d_in[4];
    const float* bk  = (const float*)d_in[5];
    const float* Wv  = (const float*)d_in[6];
    const float* bv  = (const float*)d_in[7];
    const float* Wo  = (const float*)d_in[8];
    const float* bo  = (const float*)d_in[9];
    const float* rel = (const float*)d_in[10];
    float* out = (float*)d_out;

    __half *xh, *wh, *q, *k, *v, *ctx, *ph;
    float* probs_fallback;
    unsigned char* bkt;
    cudaGetSymbolAddress((void**)&xh,  gh_x);
    cudaGetSymbolAddress((void**)&wh,  gh_w);
    cudaGetSymbolAddress((void**)&q,   gh_q);
    cudaGetSymbolAddress((void**)&k,   gh_k);
    cudaGetSymbolAddress((void**)&v,   gh_v);
    cudaGetSymbolAddress((void**)&ctx, gh_ctx);
    cudaGetSymbolAddress((void**)&ph,  gh_pr);
    cudaGetSymbolAddress((void**)&probs_fallback, g_probs);
    cudaGetSymbolAddress((void**)&bkt, g_bkt);

    float* probs = ((size_t)out_size >= OUT_ELEMS + PROB_ELEMS) ? (out + OUT_ELEMS)
                                                                : probs_fallback;

    cudaFuncSetAttribute(proj_gemm<true>,  cudaFuncAttributeMaxDynamicSharedMemorySize, SMEM_GEMM);
    cudaFuncSetAttribute(proj_gemm<false>, cudaFuncAttributeMaxDynamicSharedMemorySize, SMEM_GEMM);
    cudaFuncSetAttribute(logits_gemm,      cudaFuncAttributeMaxDynamicSharedMemorySize, SMEM_GEMM);
    cudaFuncSetAttribute(context_gemm,     cudaFuncAttributeMaxDynamicSharedMemorySize, SMEM_GEMM);

    const float scaleq = 0.022097086912079608f;  // D^-0.5 / sqrt(R)
    dim3 blk(256);

    bucket_kernel<<<(N_DIM * I_DIM * I_DIM) / 256, blk>>>(dst, bkt);

    // fp16 pre-conversion: x (33.5M elems) and the four 256x256 weights (one launch)
    conv_f16<<<(int)(OUT_ELEMS / (256 * 8)), blk>>>(x, xh);
    conv_w4<<<dim3(E_DIM * E_DIM / (256 * 8), 4), blk>>>(Wq, Wk, Wv, Wo, wh);

    dim3 pgrid(T_TOK / 128, E_DIM / 128);
    proj_gemm<true><<<pgrid, blk, SMEM_GEMM>>>(xh, wh + 0 * E_DIM * E_DIM, bq, q, scaleq);
    proj_gemm<true><<<pgrid, blk, SMEM_GEMM>>>(xh, wh + 1 * E_DIM * E_DIM, bk, k, 1.0f);
    proj_gemm<true><<<pgrid, blk, SMEM_GEMM>>>(xh, wh + 2 * E_DIM * E_DIM, bv, v, 1.0f);

    logits_gemm<<<dim3(I_DIM / 128, I_DIM / 128, N_DIM * H_DIM), blk, SMEM_GEMM>>>(
        q, k, bkt, rel, probs);
    softmax_kernel<<<(H_DIM * N_DIM * I_DIM) / 8, blk>>>(probs, ph);
    context_gemm<<<dim3(I_DIM / 128, (R_DIM * D_DIM) / 128, N_DIM * H_DIM), blk, SMEM_GEMM>>>(
        ph, v, ctx);

    proj_gemm<false><<<pgrid, blk, SMEM_GEMM>>>(ctx, wh + 3 * E_DIM * E_DIM, bo, out, 1.0f);
}

// round 9
// speedup vs baseline: 5.8290x; 1.0544x over previous
#include <cuda_runtime.h>
#include <cuda_fp16.h>
#include <math.h>
#include <stdint.h>

#define R_DIM 64
#define I_DIM 512
#define N_DIM 4
#define E_DIM 256
#define H_DIM 8
#define D_DIM 32
#define T_TOK (R_DIM * I_DIM * N_DIM)                 /* 131072 tokens */
#define OUT_ELEMS ((size_t)T_TOK * E_DIM)             /* 33554432 */
#define PROB_ELEMS ((size_t)H_DIM * N_DIM * I_DIM * I_DIM) /* 8388608 */

// KH=64 path (proj/logits): pitch 144, 3 stages.  KH=32 path (context): pitch 80, 4 stages.
#define SM64 (3 * 2 * 128 * 144)   /* 110592 */
#define SM32 (4 * 2 * 128 * 80)    /*  81920 */

// ---------------- scratch (alloc-free rule: __device__ globals) ----------------
__device__ __half gh_x[T_TOK * E_DIM];
__device__ __half gh_w[4 * E_DIM * E_DIM];
__device__ __half gh_q[T_TOK * E_DIM];
__device__ __half gh_k[T_TOK * E_DIM];
__device__ __half gh_v[T_TOK * E_DIM];
__device__ __half gh_ctx[T_TOK * E_DIM];
__device__ __half gh_pr[PROB_ELEMS];      // fp16 probs for context GEMM
__device__ float g_probs[PROB_ELEMS];     // fallback f32 probs
__device__ unsigned char g_bkt[N_DIM * I_DIM * I_DIM];

// ---------------- low-level helpers ---------------------------------------------
__device__ __forceinline__ uint32_t smem_u32(const void* p) {
    uint32_t a;
    asm("{ .reg .u64 t; cvta.to.shared.u64 t, %1; cvt.u32.u64 %0, t; }" : "=r"(a) : "l"(p));
    return a;
}
__device__ __forceinline__ void cp16(uint32_t saddr, const void* g) {
    asm volatile("cp.async.cg.shared.global [%0], [%1], 16;" :: "r"(saddr), "l"(g));
}
#define CP_COMMIT() asm volatile("cp.async.commit_group;" ::: "memory")
template<int N> __device__ __forceinline__ void cp_wait() {
    if (N == 1) asm volatile("cp.async.wait_group 1;" ::: "memory");
    else        asm volatile("cp.async.wait_group 2;" ::: "memory");
}
__device__ __forceinline__ void ldsm4(uint32_t& r0, uint32_t& r1, uint32_t& r2, uint32_t& r3,
                                      uint32_t addr) {
    asm volatile("ldmatrix.sync.aligned.m8n8.x4.shared.b16 {%0,%1,%2,%3}, [%4];"
                 : "=r"(r0), "=r"(r1), "=r"(r2), "=r"(r3) : "r"(addr));
}
__device__ __forceinline__ void ldsm4t(uint32_t& r0, uint32_t& r1, uint32_t& r2, uint32_t& r3,
                                       uint32_t addr) {
    asm volatile("ldmatrix.sync.aligned.m8n8.x4.trans.shared.b16 {%0,%1,%2,%3}, [%4];"
                 : "=r"(r0), "=r"(r1), "=r"(r2), "=r"(r3) : "r"(addr));
}
__device__ __forceinline__ void mma16816(float c[4], const uint32_t a[4], const uint32_t b[2]) {
    asm volatile(
        "mma.sync.aligned.m16n8k16.row.col.f32.f16.f16.f32 "
        "{%0,%1,%2,%3}, {%4,%5,%6,%7}, {%8,%9}, {%0,%1,%2,%3};"
        : "+f"(c[0]), "+f"(c[1]), "+f"(c[2]), "+f"(c[3])
        : "r"(a[0]), "r"(a[1]), "r"(a[2]), "r"(a[3]), "r"(b[0]), "r"(b[1]));
}

// Tile loader: 128 rows x KH halves via cp.async.
// src(row,g) = base + (row>>5)*rowGrpStride + (row&31)*rowStride + (g>>2)*kGrpStride + (g&3)*8
template<int KH>
__device__ __forceinline__ void load_tile(uint32_t sdst, const __half* base,
                                          size_t rowStride, size_t rowGrpStride,
                                          size_t kGrpStride, int tid) {
    constexpr int PITCH = KH * 2 + 16;
    constexpr int NG = KH / 8;
#pragma unroll
    for (int it = 0; it < (128 * NG) / 256; it++) {
        int idx = tid + it * 256;
        int row = idx / NG, g = idx % NG;
        const __half* src = base + (size_t)(row >> 5) * rowGrpStride
                                 + (size_t)(row & 31) * rowStride
                                 + (size_t)(g >> 2) * kGrpStride + (g & 3) * 8;
        cp16(sdst + row * PITCH + g * 16, src);
    }
}

// --------- per-warp compute on one KH-deep K chunk ------------------------------
template<int KH, bool BTRANS>
__device__ __forceinline__ void compute_chunk(uint32_t bufA, uint32_t bufB,
                                              int wm, int wn, int lane, float acc[4][4][4]) {
    constexpr int PITCH = KH * 2 + 16;
    uint32_t aoff = bufA + (uint32_t)((wm + (lane & 15)) * PITCH + ((lane >> 4) << 4));
    uint32_t boff;
    if (BTRANS) {
        boff = bufB + (uint32_t)(((wn >> 5) * 32 + (lane & 15)) * PITCH
                                 + ((lane >> 4) << 4));
    } else {
        boff = bufB + (uint32_t)((wn + ((lane >> 4) << 3) + (lane & 7)) * PITCH
                                 + (((lane >> 3) & 1) << 4));
    }
#pragma unroll
    for (int ks = 0; ks < KH / 16; ks++) {
        uint32_t a[4][4];
#pragma unroll
        for (int fq = 0; fq < 4; fq++)
            ldsm4(a[fq][0], a[fq][1], a[fq][2], a[fq][3], aoff + fq * (16 * PITCH) + ks * 32);
        uint32_t b[4][2];
        if (BTRANS) {
#pragma unroll
            for (int p = 0; p < 2; p++) {
                uint32_t r0, r1, r2, r3;
                ldsm4t(r0, r1, r2, r3, boff + ks * (16 * PITCH) + p * 32);
                b[p * 2][0] = r0; b[p * 2][1] = r1;
                b[p * 2 + 1][0] = r2; b[p * 2 + 1][1] = r3;
            }
        } else {
#pragma unroll
            for (int p = 0; p < 2; p++) {
                uint32_t r0, r1, r2, r3;
                ldsm4(r0, r1, r2, r3, boff + p * (16 * PITCH) + ks * 32);
                b[p * 2][0] = r0; b[p * 2][1] = r1;
                b[p * 2 + 1][0] = r2; b[p * 2 + 1][1] = r3;
            }
        }
#pragma unroll
        for (int fq = 0; fq < 4; fq++)
#pragma unroll
            for (int g = 0; g < 4; g++)
                mma16816(acc[fq][g], a[fq], b[g]);
    }
}

// NST-stage cp.async mainloop. NCH >= NST-1.
template<int KH, int NST, bool BTRANS>
__device__ __forceinline__ void gemm_main(
    const __half* Ab, size_t rsA, size_t rgA, size_t kgA, size_t chA,
    const __half* Bb, size_t rsB, size_t rgB, size_t kgB, size_t chB,
    int NCH, uint32_t sbase, int tid, int wm, int wn, int lane, float acc[4][4][4])
{
    constexpr int TILEB = 128 * (KH * 2 + 16);
    constexpr int STGB = 2 * TILEB;
#pragma unroll
    for (int s = 0; s < NST - 1; s++) {
        load_tile<KH>(sbase + s * STGB, Ab + (size_t)s * chA, rsA, rgA, kgA, tid);
        load_tile<KH>(sbase + s * STGB + TILEB, Bb + (size_t)s * chB, rsB, rgB, kgB, tid);
        CP_COMMIT();
    }
    int cs = 0, ls = NST - 1;
    for (int ch = 0; ch < NCH; ch++) {
        cp_wait<NST - 2>();
        __syncthreads();
        if (ch + NST - 1 < NCH) {
            uint32_t so = sbase + ls * STGB;
            load_tile<KH>(so, Ab + (size_t)(ch + NST - 1) * chA, rsA, rgA, kgA, tid);
            load_tile<KH>(so + TILEB, Bb + (size_t)(ch + NST - 1) * chB, rsB, rgB, kgB, tid);
        }
        CP_COMMIT();
        if (++ls == NST) ls = 0;
        compute_chunk<KH, BTRANS>(sbase + cs * STGB, sbase + cs * STGB + TILEB,
                                  wm, wn, lane, acc);
        if (++cs == NST) cs = 0;
    }
}

// T5 bucketize (verified exact vs jnp.linspace/searchsorted in R2/R3)
__device__ __forceinline__ int bucket_of(int dist) {
    int ad = dist < 0 ? -dist : dist;
    float v = (float)ad;
    int lo = 0, hi = 62;
#pragma unroll
    for (int it = 0; it < 6; it++) {
        int mid = (lo + hi) >> 1;
        float b = (float)((50000.0 * (double)mid) / 62.0);
        if (b >= v) hi = mid; else lo = mid + 1;
    }
    return lo;
}
__global__ __launch_bounds__(256) void bucket_kernel(
    const int* __restrict__ dist, unsigned char* __restrict__ bkt) {
    int idx = blockIdx.x * 256 + threadIdx.x;
    bkt[idx] = (unsigned char)bucket_of(dist[idx]);
}

// ---------------- f32 -> f16 bulk converts --------------------------------------
__global__ __launch_bounds__(256) void conv_f16(
    const float* __restrict__ src, __half* __restrict__ dst) {
    size_t idx = ((size_t)blockIdx.x * 256 + threadIdx.x) * 8;
    float4 a = *(const float4*)(src + idx);
    float4 b = *(const float4*)(src + idx + 4);
    __half2 h0 = __float22half2_rn(make_float2(a.x, a.y));
    __half2 h1 = __float22half2_rn(make_float2(a.z, a.w));
    __half2 h2 = __float22half2_rn(make_float2(b.x, b.y));
    __half2 h3 = __float22half2_rn(make_float2(b.z, b.w));
    uint4 u;
    u.x = *(uint32_t*)&h0; u.y = *(uint32_t*)&h1;
    u.z = *(uint32_t*)&h2; u.w = *(uint32_t*)&h3;
    *(uint4*)(dst + idx) = u;
}
__global__ __launch_bounds__(256) void conv_w4(
    const float* __restrict__ w0, const float* __restrict__ w1,
    const float* __restrict__ w2, const float* __restrict__ w3,
    __half* __restrict__ dst) {
    const float* src = (blockIdx.y == 0) ? w0 : (blockIdx.y == 1) ? w1
                      : (blockIdx.y == 2) ? w2 : w3;
    size_t idx = ((size_t)blockIdx.x * 256 + threadIdx.x) * 8;
    float4 a = *(const float4*)(src + idx);
    float4 b = *(const float4*)(src + idx + 4);
    __half2 h0 = __float22half2_rn(make_float2(a.x, a.y));
    __half2 h1 = __float22half2_rn(make_float2(a.z, a.w));
    __half2 h2 = __float22half2_rn(make_float2(b.x, b.y));
    __half2 h3 = __float22half2_rn(make_float2(b.z, b.w));
    uint4 u;
    u.x = *(uint32_t*)&h0; u.y = *(uint32_t*)&h1;
    u.z = *(uint32_t*)&h2; u.w = *(uint32_t*)&h3;
    *(uint4*)(dst + (size_t)blockIdx.y * E_DIM * E_DIM + idx) = u;
}

// ============ fused QKV projection: z selects (W, bias, out, scale) =============
__global__ __launch_bounds__(256, 2) void proj_qkv(
    const __half* __restrict__ A, const __half* __restrict__ Wall,
    const float* __restrict__ bq, const float* __restrict__ bk,
    const float* __restrict__ bv,
    __half* __restrict__ oq, __half* __restrict__ ok, __half* __restrict__ ov,
    float scaleq)
{
    extern __shared__ __align__(16) char smem[];
    const int tid = threadIdx.x, warp = tid >> 5, lane = tid & 31;
    const int wm = (warp >> 2) * 64, wn = (warp & 3) * 32;
    const int t0 = blockIdx.x * 128, f0 = blockIdx.y * 128;
    const int z = blockIdx.z;
    const __half* W = Wall + (size_t)z * E_DIM * E_DIM;
    const float* bias = (z == 0) ? bq : (z == 1) ? bk : bv;
    __half* C = (z == 0) ? oq : (z == 1) ? ok : ov;
    const float scale = (z == 0) ? scaleq : 1.0f;

    float acc[4][4][4];
#pragma unroll
    for (int fq = 0; fq < 4; fq++)
#pragma unroll
        for (int g = 0; g < 4; g++)
#pragma unroll
            for (int c = 0; c < 4; c++) acc[fq][g][c] = 0.f;

    gemm_main<64, 3, false>(
        A + (size_t)t0 * E_DIM, E_DIM, 32 * E_DIM, 32, 64,
        W + (size_t)f0 * E_DIM, E_DIM, 32 * E_DIM, 32, 64,
        E_DIM / 64, smem_u32(smem), tid, wm, wn, lane, acc);

    const int grp = lane >> 2, qid = lane & 3;
#pragma unroll
    for (int fq = 0; fq < 4; fq++)
#pragma unroll
        for (int rr = 0; rr < 2; rr++) {
            int i = t0 + wm + fq * 16 + grp + rr * 8;
#pragma unroll
            for (int g = 0; g < 4; g++) {
                int col = f0 + wn + g * 8 + qid * 2;
                float2 o;
                o.x = (acc[fq][g][rr * 2 + 0] + bias[col + 0]) * scale;
                o.y = (acc[fq][g][rr * 2 + 1] + bias[col + 1]) * scale;
                *(__half2*)(C + (size_t)i * E_DIM + col) = __float22half2_rn(o);
            }
        }
}

// ===================== output projection: f16 in, f32 out =======================
__global__ __launch_bounds__(256, 2) void proj_out(
    const __half* __restrict__ A, const __half* __restrict__ W,
    const float* __restrict__ bias, float* __restrict__ C)
{
    extern __shared__ __align__(16) char smem[];
    const int tid = threadIdx.x, warp = tid >> 5, lane = tid & 31;
    const int wm = (warp >> 2) * 64, wn = (warp & 3) * 32;
    const int t0 = blockIdx.x * 128, f0 = blockIdx.y * 128;

    float acc[4][4][4];
#pragma unroll
    for (int fq = 0; fq < 4; fq++)
#pragma unroll
        for (int g = 0; g < 4; g++)
#pragma unroll
            for (int c = 0; c < 4; c++) acc[fq][g][c] = 0.f;

    gemm_main<64, 3, false>(
        A + (size_t)t0 * E_DIM, E_DIM, 32 * E_DIM, 32, 64,
        W + (size_t)f0 * E_DIM, E_DIM, 32 * E_DIM, 32, 64,
        E_DIM / 64, smem_u32(smem), tid, wm, wn, lane, acc);

    const int grp = lane >> 2, qid = lane & 3;
#pragma unroll
    for (int fq = 0; fq < 4; fq++)
#pragma unroll
        for (int rr = 0; rr < 2; rr++) {
            int i = t0 + wm + fq * 16 + grp + rr * 8;
#pragma unroll
            for (int g = 0; g < 4; g++) {
                int col = f0 + wn + g * 8 + qid * 2;
                float2 o;
                o.x = acc[fq][g][rr * 2 + 0] + bias[col + 0];
                o.y = acc[fq][g][rr * 2 + 1] + bias[col + 1];
                *(float2*)(C + (size_t)i * E_DIM + col) = o;
            }
        }
}

// =========== logits: out[h,n,i,j] = sum_{r,d} q·k + rel[bucket[n,i,j],h] =========
__global__ __launch_bounds__(256, 2) void logits_gemm(
    const __half* __restrict__ q, const __half* __restrict__ k,
    const unsigned char* __restrict__ bkt, const float* __restrict__ rel,
    float* __restrict__ out)
{
    extern __shared__ __align__(16) char smem[];
    const int tid = threadIdx.x, warp = tid >> 5, lane = tid & 31;
    const int wm = (warp >> 2) * 64, wn = (warp & 3) * 32;
    const int i0 = blockIdx.x * 128, j0 = blockIdx.y * 128;
    const int z = blockIdx.z, h = z >> 2, n = z & 3;

    float acc[4][4][4];
#pragma unroll
    for (int fq = 0; fq < 4; fq++)
#pragma unroll
        for (int g = 0; g < 4; g++)
#pragma unroll
            for (int c = 0; c < 4; c++) acc[fq][g][c] = 0.f;

    // K chunk = 2 r values: [r0 d0..31 | r1 d0..31]; same packing both operands.
    gemm_main<64, 3, false>(
        q + ((size_t)i0 * 4 + n) * 256 + h * 32, 1024, 32 * 1024, 524288, 1048576,
        k + ((size_t)j0 * 4 + n) * 256 + h * 32, 1024, 32 * 1024, 524288, 1048576,
        32, smem_u32(smem), tid, wm, wn, lane, acc);

    const int grp = lane >> 2, qid = lane & 3;
#pragma unroll
    for (int fq = 0; fq < 4; fq++)
#pragma unroll
        for (int rr = 0; rr < 2; rr++) {
            int i = i0 + wm + fq * 16 + grp + rr * 8;
            const unsigned char* brow = bkt + ((size_t)n * I_DIM + i) * I_DIM;
            float* orow = out + ((size_t)(h * 4 + n) * I_DIM + i) * I_DIM;
#pragma unroll
            for (int g = 0; g < 4; g++) {
                int j = j0 + wn + g * 8 + qid * 2;
                float2 o;
                o.x = acc[fq][g][rr * 2 + 0] + rel[brow[j + 0] * H_DIM + h];
                o.y = acc[fq][g][rr * 2 + 1] + rel[brow[j + 1] * H_DIM + h];
                *(float2*)(orow + j) = o;
            }
        }
}

// --------- softmax over last dim (512): 1 warp/row, 8 rows/block, no smem -------
__global__ __launch_bounds__(256) void softmax_kernel(
    float* __restrict__ P, __half* __restrict__ Ph) {
    const size_t row = (size_t)blockIdx.x * 8 + (threadIdx.x >> 5);
    const int lane = threadIdx.x & 31;
    float* p = P + row * 512;
    __half* ph = Ph + row * 512;

    float4 xv[4];
#pragma unroll
    for (int it = 0; it < 4; it++) xv[it] = ((float4*)p)[lane + it * 32];

    float m = -1e30f;
#pragma unroll
    for (int it = 0; it < 4; it++)
        m = fmaxf(m, fmaxf(fmaxf(xv[it].x, xv[it].y), fmaxf(xv[it].z, xv[it].w)));
#pragma unroll
    for (int o = 16; o > 0; o >>= 1) m = fmaxf(m, __shfl_xor_sync(0xffffffffu, m, o));

    float s = 0.f;
#pragma unroll
    for (int it = 0; it < 4; it++) {
        xv[it].x = expf(xv[it].x - m); xv[it].y = expf(xv[it].y - m);
        xv[it].z = expf(xv[it].z - m); xv[it].w = expf(xv[it].w - m);
        s += xv[it].x + xv[it].y + xv[it].z + xv[it].w;
    }
#pragma unroll
    for (int o = 16; o > 0; o >>= 1) s += __shfl_xor_sync(0xffffffffu, s, o);
    float inv = 1.0f / s;

#pragma unroll
    for (int it = 0; it < 4; it++) {
        xv[it].x *= inv; xv[it].y *= inv; xv[it].z *= inv; xv[it].w *= inv;
        ((float4*)p)[lane + it * 32] = xv[it];
        __half2 h0 = __float22half2_rn(make_float2(xv[it].x, xv[it].y));
        __half2 h1 = __float22half2_rn(make_float2(xv[it].z, xv[it].w));
        uint2 u; u.x = *(uint32_t*)&h0; u.y = *(uint32_t*)&h1;
        *(uint2*)(ph + (lane + it * 32) * 4) = u;
    }
}

// ===== context: ctx[r,i,n,h,d] = sum_j P[h,n,i,j] v[r,j,n,h,d]  (trans-B) ========
__global__ __launch_bounds__(256, 2) void context_gemm(
    const __half* __restrict__ Ph, const __half* __restrict__ v,
    __half* __restrict__ ctx)
{
    extern __shared__ __align__(16) char smem[];
    const int tid = threadIdx.x, warp = tid >> 5, lane = tid & 31;
    const int wm = (warp >> 2) * 64, wn = (warp & 3) * 32;
    const int i0 = blockIdx.x * 128;
    const int c0 = blockIdx.y * 128;      // over r*32+d (2048 wide)
    const int r0 = c0 >> 5;               // 4 r values per tile
    const int z = blockIdx.z, h = z >> 2, n = z & 3;
    const int nh = h * 4 + n;

    float acc[4][4][4];
#pragma unroll
    for (int fq = 0; fq < 4; fq++)
#pragma unroll
        for (int g = 0; g < 4; g++)
#pragma unroll
            for (int c = 0; c < 4; c++) acc[fq][g][c] = 0.f;

    gemm_main<32, 4, true>(
        Ph + ((size_t)nh * 512 + i0) * 512, 512, 32 * 512, 0, 32,
        v + ((size_t)r0 * 512 * 4 + n) * 256 + h * 32, 1024, 524288, 0, 32768,
        16, smem_u32(smem), tid, wm, wn, lane, acc);

    const int grp = lane >> 2, qid = lane & 3;
#pragma unroll
    for (int fq = 0; fq < 4; fq++)
#pragma unroll
        for (int rr = 0; rr < 2; rr++) {
            int i = i0 + wm + fq * 16 + grp + rr * 8;
#pragma unroll
            for (int g = 0; g < 4; g++) {
                int col = c0 + wn + g * 8 + qid * 2;
                int r = col >> 5, d = col & 31;
                float2 o;
                o.x = acc[fq][g][rr * 2 + 0];
                o.y = acc[fq][g][rr * 2 + 1];
                *(__half2*)(ctx + (((size_t)r * 512 + i) * 4 + n) * 256 + h * 32 + d) =
                    __float22half2_rn(o);
            }
        }
}

// --------------------------------- launch ---------------------------------------
extern "C" void kernel_launch(void* const* d_in, const int* in_sizes, int n_in,
                              void* d_out, int out_size) {
    const float* x   = (const float*)d_in[0];
    const int*   dst = (const int*)  d_in[1];
    const float* Wq  = (const float*)d_in[2];
    const float* bq  = (const float*)d_in[3];
    const float* Wk  = (const float*)d_in[4];
    const float* bk  = (const float*)d_in[5];
    const float* Wv  = (const float*)d_in[6];
    const float* bv  = (const float*)d_in[7];
    const float* Wo  = (const float*)d_in[8];
    const float* bo  = (const float*)d_in[9];
    const float* rel = (const float*)d_in[10];
    float* out = (float*)d_out;

    __half *xh, *wh, *q, *k, *v, *ctx, *ph;
    float* probs_fallback;
    unsigned char* bkt;
    cudaGetSymbolAddress((void**)&xh,  gh_x);
    cudaGetSymbolAddress((void**)&wh,  gh_w);
    cudaGetSymbolAddress((void**)&q,   gh_q);
    cudaGetSymbolAddress((void**)&k,   gh_k);
    cudaGetSymbolAddress((void**)&v,   gh_v);
    cudaGetSymbolAddress((void**)&ctx, gh_ctx);
    cudaGetSymbolAddress((void**)&ph,  gh_pr);
    cudaGetSymbolAddress((void**)&probs_fallback, g_probs);
    cudaGetSymbolAddress((void**)&bkt, g_bkt);

    float* probs = ((size_t)out_size >= OUT_ELEMS + PROB_ELEMS) ? (out + OUT_ELEMS)
                                                                : probs_fallback;

    cudaFuncSetAttribute(proj_qkv,     cudaFuncAttributeMaxDynamicSharedMemorySize, SM64);
    cudaFuncSetAttribute(proj_out,     cudaFuncAttributeMaxDynamicSharedMemorySize, SM64);
    cudaFuncSetAttribute(logits_gemm,  cudaFuncAttributeMaxDynamicSharedMemorySize, SM64);
    cudaFuncSetAttribute(context_gemm, cudaFuncAttributeMaxDynamicSharedMemorySize, SM32);

    const float scaleq = 0.022097086912079608f;  // D^-0.5 / sqrt(R)
    dim3 blk(256);

    bucket_kernel<<<(N_DIM * I_DIM * I_DIM) / 256, blk>>>(dst, bkt);

    // fp16 pre-conversion: x and the four 256x256 weights (wh order: Wq,Wk,Wv,Wo)
    conv_f16<<<(int)(OUT_ELEMS / (256 * 8)), blk>>>(x, xh);
    conv_w4<<<dim3(E_DIM * E_DIM / (256 * 8), 4), blk>>>(Wq, Wk, Wv, Wo, wh);

    proj_qkv<<<dim3(T_TOK / 128, E_DIM / 128, 3), blk, SM64>>>(
        xh, wh, bq, bk, bv, q, k, v, scaleq);

    logits_gemm<<<dim3(I_DIM / 128, I_DIM / 128, N_DIM * H_DIM), blk, SM64>>>(
        q, k, bkt, rel, probs);
    softmax_kernel<<<(H_DIM * N_DIM * I_DIM) / 8, blk>>>(probs, ph);
    context_gemm<<<dim3(I_DIM / 128, (R_DIM * D_DIM) / 128, N_DIM * H_DIM), blk, SM32>>>(
        ph, v, ctx);

    proj_out<<<dim3(T_TOK / 128, E_DIM / 128), blk, SM64>>>(
        ctx, wh + 3 * E_DIM * E_DIM, bo, out);
}